// round 1
// baseline (speedup 1.0000x reference)
#include <cuda_runtime.h>
#include <math.h>

#define NH 16
#define DM 1024
#define DH 64
#define BB 2
#define TT 2048

// Scratch: __device__ globals (no runtime allocation allowed).
__device__ float g_qkv[(size_t)BB * TT * 3 * DM];          // [b, t, 3*1024]
__device__ float g_ctx[(size_t)BB * TT * DM];              // [b, t, 1024]
__device__ float g_attn_fallback[(size_t)BB * NH * TT * TT]; // used only if d_out lacks attn

// ---------------------------------------------------------------------------
// Generic 64x64x16 tiled SGEMM, C = alpha * A * B^T  (A[M,K] row-major lda,
// B[N,K] row-major ldb -> "NT"). Batched over blockIdx.z with separate
// (batch, head) strides: bz = b*NH + h.
// causalSkip: skip tiles strictly above the diagonal (keys > queries).
// ---------------------------------------------------------------------------
__global__ __launch_bounds__(256) void gemm_nt(
    const float* __restrict__ A, const float* __restrict__ B, float* __restrict__ C,
    int M, int N, int K, int lda, int ldb, int ldc,
    long long sAb, long long sAh, long long sBb, long long sBh,
    long long sCb, long long sCh,
    float alpha, int causalSkip)
{
    int bx = blockIdx.x, by = blockIdx.y, bz = blockIdx.z;
    if (causalSkip && bx > by) return;   // whole tile masked; softmax writes zeros there

    int b = bz >> 4;   // NH == 16
    int h = bz & 15;
    A += (size_t)b * sAb + (size_t)h * sAh;
    B += (size_t)b * sBb + (size_t)h * sBh;
    C += (size_t)b * sCb + (size_t)h * sCh;

    __shared__ float As[16][68];
    __shared__ float Bs[16][68];

    int tid = threadIdx.x;
    int tx = tid & 15, ty = tid >> 4;     // 16x16 thread grid, 4x4 microtile
    int row0 = by * 64, col0 = bx * 64;

    int lr  = tid >> 2;         // 0..63: tile row loaded by this thread
    int lk4 = (tid & 3) * 4;    // 0,4,8,12: k-quad

    float acc[4][4];
#pragma unroll
    for (int i = 0; i < 4; i++)
#pragma unroll
        for (int j = 0; j < 4; j++) acc[i][j] = 0.f;

    for (int k0 = 0; k0 < K; k0 += 16) {
        float4 av = *(const float4*)(A + (size_t)(row0 + lr) * lda + k0 + lk4);
        float4 bv = *(const float4*)(B + (size_t)(col0 + lr) * ldb + k0 + lk4);
        As[lk4 + 0][lr] = av.x; As[lk4 + 1][lr] = av.y;
        As[lk4 + 2][lr] = av.z; As[lk4 + 3][lr] = av.w;
        Bs[lk4 + 0][lr] = bv.x; Bs[lk4 + 1][lr] = bv.y;
        Bs[lk4 + 2][lr] = bv.z; Bs[lk4 + 3][lr] = bv.w;
        __syncthreads();
#pragma unroll
        for (int k = 0; k < 16; k++) {
            float4 a = *(const float4*)&As[k][ty * 4];
            float4 bq = *(const float4*)&Bs[k][tx * 4];
            acc[0][0] += a.x * bq.x; acc[0][1] += a.x * bq.y; acc[0][2] += a.x * bq.z; acc[0][3] += a.x * bq.w;
            acc[1][0] += a.y * bq.x; acc[1][1] += a.y * bq.y; acc[1][2] += a.y * bq.z; acc[1][3] += a.y * bq.w;
            acc[2][0] += a.z * bq.x; acc[2][1] += a.z * bq.y; acc[2][2] += a.z * bq.z; acc[2][3] += a.z * bq.w;
            acc[3][0] += a.w * bq.x; acc[3][1] += a.w * bq.y; acc[3][2] += a.w * bq.z; acc[3][3] += a.w * bq.w;
        }
        __syncthreads();
    }

#pragma unroll
    for (int i = 0; i < 4; i++) {
        float4 v = make_float4(alpha * acc[i][0], alpha * acc[i][1],
                               alpha * acc[i][2], alpha * acc[i][3]);
        *(float4*)&C[(size_t)(row0 + ty * 4 + i) * ldc + col0 + tx * 4] = v;
    }
}

// ---------------------------------------------------------------------------
// 64x64x16 tiled SGEMM, C = A * B  (A[M,K] lda row-major, B[K,N] ldb row-major
// -> "NN"). Used for context = attn @ V (N = 64). causalClamp: K limited to
// keys <= max query of this row tile (rows beyond are exact zeros in attn).
// ---------------------------------------------------------------------------
__global__ __launch_bounds__(256) void gemm_nn(
    const float* __restrict__ A, const float* __restrict__ B, float* __restrict__ C,
    int M, int N, int K, int lda, int ldb, int ldc,
    long long sAb, long long sAh, long long sBb, long long sBh,
    long long sCb, long long sCh,
    int causalClamp)
{
    int bx = blockIdx.x, by = blockIdx.y, bz = blockIdx.z;
    int b = bz >> 4;
    int h = bz & 15;
    A += (size_t)b * sAb + (size_t)h * sAh;
    B += (size_t)b * sBb + (size_t)h * sBh;
    C += (size_t)b * sCb + (size_t)h * sCh;

    __shared__ float As[16][68];
    __shared__ float Bs[16][68];

    int tid = threadIdx.x;
    int tx = tid & 15, ty = tid >> 4;
    int row0 = by * 64, col0 = bx * 64;

    int lr  = tid >> 2;
    int lk4 = (tid & 3) * 4;
    int kr  = tid >> 4;          // 0..15: B tile k-row
    int ln4 = (tid & 15) * 4;    // 0..60: B tile n-quad

    int Keff = causalClamp ? min(K, (by + 1) * 64) : K;

    float acc[4][4];
#pragma unroll
    for (int i = 0; i < 4; i++)
#pragma unroll
        for (int j = 0; j < 4; j++) acc[i][j] = 0.f;

    for (int k0 = 0; k0 < Keff; k0 += 16) {
        float4 av = *(const float4*)(A + (size_t)(row0 + lr) * lda + k0 + lk4);
        float4 bv = *(const float4*)(B + (size_t)(k0 + kr) * ldb + col0 + ln4);
        As[lk4 + 0][lr] = av.x; As[lk4 + 1][lr] = av.y;
        As[lk4 + 2][lr] = av.z; As[lk4 + 3][lr] = av.w;
        *(float4*)&Bs[kr][ln4] = bv;
        __syncthreads();
#pragma unroll
        for (int k = 0; k < 16; k++) {
            float4 a = *(const float4*)&As[k][ty * 4];
            float4 bq = *(const float4*)&Bs[k][tx * 4];
            acc[0][0] += a.x * bq.x; acc[0][1] += a.x * bq.y; acc[0][2] += a.x * bq.z; acc[0][3] += a.x * bq.w;
            acc[1][0] += a.y * bq.x; acc[1][1] += a.y * bq.y; acc[1][2] += a.y * bq.z; acc[1][3] += a.y * bq.w;
            acc[2][0] += a.z * bq.x; acc[2][1] += a.z * bq.y; acc[2][2] += a.z * bq.z; acc[2][3] += a.z * bq.w;
            acc[3][0] += a.w * bq.x; acc[3][1] += a.w * bq.y; acc[3][2] += a.w * bq.z; acc[3][3] += a.w * bq.w;
        }
        __syncthreads();
    }

#pragma unroll
    for (int i = 0; i < 4; i++) {
        float4 v = make_float4(acc[i][0], acc[i][1], acc[i][2], acc[i][3]);
        *(float4*)&C[(size_t)(row0 + ty * 4 + i) * ldc + col0 + tx * 4] = v;
    }
}

// ---------------------------------------------------------------------------
// Causal row softmax, in place over attn[(b*NH+h)*T + q] rows of length T.
// Valid length = q+1; masked tail written as exact 0 (matches softmax(-inf)).
// ---------------------------------------------------------------------------
__global__ __launch_bounds__(256) void softmax_rows(float* __restrict__ attn)
{
    __shared__ float red[256];
    size_t r = blockIdx.x;             // over BB*NH*TT rows
    int q = (int)(r & (TT - 1));
    float* row = attn + r * (size_t)TT;
    int len = q + 1;
    int tid = threadIdx.x;

    float m = -INFINITY;
    for (int i = tid; i < len; i += 256) m = fmaxf(m, row[i]);
    red[tid] = m; __syncthreads();
#pragma unroll
    for (int s = 128; s > 0; s >>= 1) {
        if (tid < s) red[tid] = fmaxf(red[tid], red[tid + s]);
        __syncthreads();
    }
    m = red[0];
    __syncthreads();

    float sum = 0.f;
    for (int i = tid; i < len; i += 256) sum += __expf(row[i] - m);
    red[tid] = sum; __syncthreads();
#pragma unroll
    for (int s = 128; s > 0; s >>= 1) {
        if (tid < s) red[tid] += red[tid + s];
        __syncthreads();
    }
    float inv = 1.0f / red[0];
    __syncthreads();

    for (int i = tid; i < len; i += 256) row[i] = __expf(row[i] - m) * inv;
    for (int i = len + tid; i < TT; i += 256) row[i] = 0.f;
}

// ---------------------------------------------------------------------------
extern "C" void kernel_launch(void* const* d_in, const int* in_sizes, int n_in,
                              void* d_out, int out_size)
{
    const float* x      = (const float*)d_in[0];   // [2, 2048, 1024]
    const float* w_qkv  = (const float*)d_in[1];   // [3072, 1024]
    const float* w_proj = (const float*)d_in[2];   // [1024, 1024]
    float* out = (float*)d_out;

    float *qkv, *ctx, *attn_fb;
    cudaGetSymbolAddress((void**)&qkv, g_qkv);
    cudaGetSymbolAddress((void**)&ctx, g_ctx);
    cudaGetSymbolAddress((void**)&attn_fb, g_attn_fallback);

    const size_t out_elems = (size_t)BB * TT * DM;            // 4,194,304
    float* attn = ((size_t)out_size > out_elems) ? (out + out_elems) : attn_fb;

    const int M = BB * TT;            // 4096 tokens
    const float scale = 1.0f / 8.0f;  // 1/sqrt(64)

    // 1) qkv = x @ w_qkv^T : [4096,1024] x [3072,1024]^T -> [4096,3072]
    gemm_nt<<<dim3(3 * DM / 64, M / 64, 1), 256>>>(
        x, w_qkv, qkv, M, 3 * DM, DM, DM, DM, 3 * DM,
        0, 0, 0, 0, 0, 0, 1.0f, 0);

    // 2) scores = q @ k^T * scale, per (b,h). q at qkv[...,0:1024], k at +1024.
    //    Tiles strictly above the diagonal are skipped entirely.
    gemm_nt<<<dim3(TT / 64, TT / 64, BB * NH), 256>>>(
        qkv, qkv + DM, attn, TT, TT, DH, 3 * DM, 3 * DM, TT,
        (long long)TT * 3 * DM, DH,                // A strides (b, h)
        (long long)TT * 3 * DM, DH,                // B strides
        (long long)NH * TT * TT, (long long)TT * TT, // C strides
        scale, 1);

    // 3) causal softmax in place (also zeroes the masked/unwritten region)
    softmax_rows<<<BB * NH * TT, 256>>>(attn);

    // 4) ctx = attn @ v, per (b,h). v at qkv[...,+2048]. K clamped causally.
    gemm_nn<<<dim3(1, TT / 64, BB * NH), 256>>>(
        attn, qkv + 2 * DM, ctx, TT, DH, TT, TT, 3 * DM, DM,
        (long long)NH * TT * TT, (long long)TT * TT,
        (long long)TT * 3 * DM, DH,
        (long long)TT * DM, DH,
        1);

    // 5) out = ctx @ w_proj^T : [4096,1024] x [1024,1024]^T -> [4096,1024]
    gemm_nt<<<dim3(DM / 64, M / 64, 1), 256>>>(
        ctx, w_proj, out, M, DM, DM, DM, DM, DM,
        0, 0, 0, 0, 0, 0, 1.0f, 0);
}

// round 3
// speedup vs baseline: 1.7413x; 1.7413x over previous
#include <cuda_runtime.h>
#include <cuda_bf16.h>
#include <cstdint>
#include <math.h>

#define NH 16
#define DM 1024
#define DH 64
#define BB 2
#define TT 2048

typedef unsigned short ushort_t;

// ---------------------------------------------------------------------------
// Scratch (__device__ globals). Split format: x ~= hi + lo (both bf16),
// stored as separate arrays for direct cp.async.
// ---------------------------------------------------------------------------
__device__ ushort_t g_xh[(size_t)BB * TT * DM];
__device__ ushort_t g_xl[(size_t)BB * TT * DM];
__device__ ushort_t g_wqkvh[(size_t)3 * DM * DM];
__device__ ushort_t g_wqkvl[(size_t)3 * DM * DM];
__device__ ushort_t g_wprojh[(size_t)DM * DM];
__device__ ushort_t g_wprojl[(size_t)DM * DM];
__device__ float    g_qkv[(size_t)BB * TT * 3 * DM];
__device__ ushort_t g_qkvh[(size_t)BB * TT * 3 * DM];
__device__ ushort_t g_qkvl[(size_t)BB * TT * 3 * DM];
__device__ ushort_t g_vth[(size_t)BB * NH * DH * TT];   // V^T per head [64][2048]
__device__ ushort_t g_vtl[(size_t)BB * NH * DH * TT];
__device__ ushort_t g_ph[(size_t)BB * NH * TT * TT];    // split attn probs
__device__ ushort_t g_pl[(size_t)BB * NH * TT * TT];
__device__ float    g_ctx[(size_t)BB * TT * DM];
__device__ ushort_t g_ctxh[(size_t)BB * TT * DM];
__device__ ushort_t g_ctxl[(size_t)BB * TT * DM];
__device__ float    g_attn_fallback[(size_t)BB * NH * TT * TT];

// ---------------------------------------------------------------------------
__device__ __forceinline__ uint32_t smem_u32(const void* p) {
    uint32_t a;
    asm("{ .reg .u64 t; cvta.to.shared.u64 t, %1; cvt.u32.u64 %0, t; }" : "=r"(a) : "l"(p));
    return a;
}
__device__ __forceinline__ void cp16(uint32_t dst, const void* src) {
    unsigned long long g = (unsigned long long)__cvta_generic_to_global(src);
    asm volatile("cp.async.cg.shared.global [%0], [%1], 16;" :: "r"(dst), "l"(g));
}
#define CP_COMMIT() asm volatile("cp.async.commit_group;" ::: "memory")
#define CP_WAIT2()  asm volatile("cp.async.wait_group 2;" ::: "memory")

__device__ __forceinline__ void ldsm4(uint32_t* r, uint32_t addr) {
    asm volatile("ldmatrix.sync.aligned.m8n8.x4.shared.b16 {%0,%1,%2,%3}, [%4];"
        : "=r"(r[0]), "=r"(r[1]), "=r"(r[2]), "=r"(r[3]) : "r"(addr));
}
__device__ __forceinline__ void mma16816(float* c, const uint32_t* a, uint32_t b0, uint32_t b1) {
    asm volatile("mma.sync.aligned.m16n8k16.row.col.f32.bf16.bf16.f32 "
        "{%0,%1,%2,%3}, {%4,%5,%6,%7}, {%8,%9}, {%0,%1,%2,%3};"
        : "+f"(c[0]), "+f"(c[1]), "+f"(c[2]), "+f"(c[3])
        : "r"(a[0]), "r"(a[1]), "r"(a[2]), "r"(a[3]), "r"(b0), "r"(b1));
}

__device__ __forceinline__ void split2(float x, ushort_t& h, ushort_t& l) {
    __nv_bfloat16 hb = __float2bfloat16(x);
    float hf = __bfloat162float(hb);
    __nv_bfloat16 lb = __float2bfloat16(x - hf);
    h = __bfloat16_as_ushort(hb);
    l = __bfloat16_as_ushort(lb);
}

// ---------------------------------------------------------------------------
// Split fp32 array into hi/lo bf16 arrays (vectorized by 4).
// ---------------------------------------------------------------------------
__global__ __launch_bounds__(256) void split_arr(const float4* __restrict__ in,
                                                 ushort4* __restrict__ hi,
                                                 ushort4* __restrict__ lo, int n4) {
    int i = blockIdx.x * 256 + threadIdx.x;
    if (i < n4) {
        float4 v = in[i];
        ushort4 h, l;
        split2(v.x, h.x, l.x); split2(v.y, h.y, l.y);
        split2(v.z, h.z, l.z); split2(v.w, h.w, l.w);
        hi[i] = h; lo[i] = l;
    }
}

// ---------------------------------------------------------------------------
// Transpose+split V: vt[(bh*64+d)*2048 + t] from qkv[(b*T+t)*3072 + 2048 + h*64 + d]
// ---------------------------------------------------------------------------
__global__ __launch_bounds__(256) void transpose_v(const float* __restrict__ qkv,
                                                   ushort_t* __restrict__ vth,
                                                   ushort_t* __restrict__ vtl) {
    __shared__ uint32_t tile[32][33];
    int bh = blockIdx.z;
    int b = bh >> 4, h = bh & 15;
    int t0 = blockIdx.y * 32, d0 = blockIdx.x * 32;
    int tx = threadIdx.x, ty = threadIdx.y;
#pragma unroll
    for (int j = 0; j < 4; j++) {
        int t = t0 + ty + j * 8;
        int d = d0 + tx;
        ushort_t hh, ll;
        split2(qkv[((size_t)b * TT + t) * (3 * DM) + 2 * DM + h * DH + d], hh, ll);
        tile[ty + j * 8][tx] = (uint32_t)hh | ((uint32_t)ll << 16);
    }
    __syncthreads();
#pragma unroll
    for (int j = 0; j < 4; j++) {
        int d = d0 + ty + j * 8;
        int t = t0 + tx;
        uint32_t v = tile[tx][ty + j * 8];
        size_t idx = ((size_t)bh * DH + d) * TT + t;
        vth[idx] = (ushort_t)(v & 0xFFFF);
        vtl[idx] = (ushort_t)(v >> 16);
    }
}

// ---------------------------------------------------------------------------
// Split-bf16 tensor-core GEMM via mma.sync: C[M,N] = alpha * A[M,K] * B[N,K]^T.
// BM=128 fixed, BN in {64,128}. 256 threads, 8 warps (4 x 2), warp tile 32x(BN/2).
// 3-stage cp.async pipeline, KC=16. Smem rows padded to 48B (conflict-free ldmatrix).
// CMODE: 0 none, 1 causal tile skip (scores), 2 causal K clamp (ctx).
// ---------------------------------------------------------------------------
template <int BN, int CMODE>
__global__ __launch_bounds__(256) void gemm_mma(
    const ushort_t* __restrict__ Ahp, const ushort_t* __restrict__ Alp,
    const ushort_t* __restrict__ Bhp, const ushort_t* __restrict__ Blp,
    float* __restrict__ C,
    int K, int lda, int ldb, int ldc,
    long long sAb, long long sAh, long long sBb, long long sBh,
    long long sCb, long long sCh, float alpha)
{
    constexpr int NP = BN / 32;               // B n16-pairs per warp
    constexpr int A_BYTES = 128 * 48;
    constexpr int B_BYTES = BN * 48;
    constexpr int STAGE = 2 * A_BYTES + 2 * B_BYTES;
    constexpr int OFF_AH = 0, OFF_AL = A_BYTES, OFF_BH = 2 * A_BYTES, OFF_BL = 2 * A_BYTES + B_BYTES;

    int bx = blockIdx.x, by = blockIdx.y, bz = blockIdx.z;
    int row0 = by * 128, col0 = bx * BN;
    if (CMODE == 1 && col0 > row0 + 127) return;

    int b = bz >> 4, h = bz & 15;
    Ahp += (size_t)b * sAb + (size_t)h * sAh;
    Alp += (size_t)b * sAb + (size_t)h * sAh;
    Bhp += (size_t)b * sBb + (size_t)h * sBh;
    Blp += (size_t)b * sBb + (size_t)h * sBh;
    C   += (size_t)b * sCb + (size_t)h * sCh;

    extern __shared__ char smraw[];
    uint32_t smb = smem_u32(smraw);

    int tid = threadIdx.x;
    int wid = tid >> 5, L = tid & 31;
    int warp_row = (wid & 3) * 32;
    int warp_col = (wid >> 2) * (BN / 2);

    int Keff = (CMODE == 2) ? min(K, row0 + 128) : K;
    int nc = Keff >> 4;

    // per-thread load mapping
    int arow = tid >> 1, achk = tid & 1;              // A: 128 rows x 2 chunks
    const ushort_t* aSrcH = Ahp + (size_t)(row0 + arow) * lda + achk * 8;
    const ushort_t* aSrcL = Alp + (size_t)(row0 + arow) * lda + achk * 8;
    uint32_t aDst = (uint32_t)(arow * 48 + achk * 16);
    bool bAct = tid < 2 * BN;
    int brow = arow, bchk = achk;
    const ushort_t* bSrcH = Bhp + (size_t)(col0 + brow) * ldb + bchk * 8;
    const ushort_t* bSrcL = Blp + (size_t)(col0 + brow) * ldb + bchk * 8;
    uint32_t bDst = (uint32_t)(brow * 48 + bchk * 16);

    // ldmatrix lane addressing
    int ldrow = ((L >> 3) & 1) * 8 + (L & 7);
    int ldkb  = (L >> 4) * 16;

    float acc[2][2 * NP][4];
#pragma unroll
    for (int i = 0; i < 2; i++)
#pragma unroll
        for (int j = 0; j < 2 * NP; j++)
#pragma unroll
            for (int q = 0; q < 4; q++) acc[i][j][q] = 0.f;

    // prologue: stages 0,1
#pragma unroll
    for (int s = 0; s < 2; s++) {
        if (s < nc) {
            uint32_t sb = smb + s * STAGE;
            int k0 = s * 16;
            cp16(sb + OFF_AH + aDst, aSrcH + k0);
            cp16(sb + OFF_AL + aDst, aSrcL + k0);
            if (bAct) { cp16(sb + OFF_BH + bDst, bSrcH + k0); cp16(sb + OFF_BL + bDst, bSrcL + k0); }
        }
        CP_COMMIT();
    }

    for (int ch = 0; ch < nc; ch++) {
        int sNext = ch + 2;
        if (sNext < nc) {
            uint32_t sb = smb + (sNext % 3) * STAGE;
            int k0 = sNext * 16;
            cp16(sb + OFF_AH + aDst, aSrcH + k0);
            cp16(sb + OFF_AL + aDst, aSrcL + k0);
            if (bAct) { cp16(sb + OFF_BH + bDst, bSrcH + k0); cp16(sb + OFF_BL + bDst, bSrcL + k0); }
        }
        CP_COMMIT();
        CP_WAIT2();
        __syncthreads();

        uint32_t sb = smb + (ch % 3) * STAGE;
        uint32_t ah[2][4], al[2][4];
#pragma unroll
        for (int mt = 0; mt < 2; mt++) {
            uint32_t ra = (uint32_t)((warp_row + mt * 16 + ldrow) * 48 + ldkb);
            ldsm4(ah[mt], sb + OFF_AH + ra);
            ldsm4(al[mt], sb + OFF_AL + ra);
        }
#pragma unroll
        for (int np = 0; np < NP; np++) {
            uint32_t rb = (uint32_t)((warp_col + np * 16 + ldrow) * 48 + ldkb);
            uint32_t bh[4], bl[4];
            ldsm4(bh, sb + OFF_BH + rb);
            ldsm4(bl, sb + OFF_BL + rb);
#pragma unroll
            for (int mt = 0; mt < 2; mt++) {
                mma16816(acc[mt][2 * np],     ah[mt], bh[0], bh[2]);
                mma16816(acc[mt][2 * np],     ah[mt], bl[0], bl[2]);
                mma16816(acc[mt][2 * np],     al[mt], bh[0], bh[2]);
                mma16816(acc[mt][2 * np + 1], ah[mt], bh[1], bh[3]);
                mma16816(acc[mt][2 * np + 1], ah[mt], bl[1], bl[3]);
                mma16816(acc[mt][2 * np + 1], al[mt], bh[1], bh[3]);
            }
        }
        __syncthreads();
    }

    // epilogue: c-frag thread T: rows T/4 and T/4+8, cols (T%4)*2,+1
#pragma unroll
    for (int mt = 0; mt < 2; mt++) {
        int r0g = row0 + warp_row + mt * 16 + (L >> 2);
#pragma unroll
        for (int nt = 0; nt < 2 * NP; nt++) {
            int cg = col0 + warp_col + nt * 8 + (L & 3) * 2;
            float* p0 = C + (size_t)r0g * ldc + cg;
            float* p1 = C + (size_t)(r0g + 8) * ldc + cg;
            *(float2*)p0 = make_float2(alpha * acc[mt][nt][0], alpha * acc[mt][nt][1]);
            *(float2*)p1 = make_float2(alpha * acc[mt][nt][2], alpha * acc[mt][nt][3]);
        }
    }
}

// ---------------------------------------------------------------------------
// Fused causal softmax: normalized fp32 row (exact zeros in tail) + split probs.
// ---------------------------------------------------------------------------
__global__ __launch_bounds__(256) void softmax_split(float* __restrict__ attn,
                                                     ushort_t* __restrict__ ph,
                                                     ushort_t* __restrict__ pl) {
    __shared__ float red[256];
    size_t r = blockIdx.x;
    int q = (int)(r & (TT - 1));
    int len = q + 1;
    int keff = ((q >> 7) << 7) + 128;
    float* row = attn + r * (size_t)TT;
    int tid = threadIdx.x;
    int base = tid * 8;

    float4 v0 = *(const float4*)(row + base);
    float4 v1 = *(const float4*)(row + base + 4);
    float vals[8] = {v0.x, v0.y, v0.z, v0.w, v1.x, v1.y, v1.z, v1.w};

    float m = -INFINITY;
#pragma unroll
    for (int j = 0; j < 8; j++) if (base + j < len) m = fmaxf(m, vals[j]);
    red[tid] = m; __syncthreads();
#pragma unroll
    for (int s = 128; s > 0; s >>= 1) {
        if (tid < s) red[tid] = fmaxf(red[tid], red[tid + s]);
        __syncthreads();
    }
    m = red[0]; __syncthreads();

    float e[8]; float sum = 0.f;
#pragma unroll
    for (int j = 0; j < 8; j++) {
        e[j] = (base + j < len) ? __expf(vals[j] - m) : 0.f;
        sum += e[j];
    }
    red[tid] = sum; __syncthreads();
#pragma unroll
    for (int s = 128; s > 0; s >>= 1) {
        if (tid < s) red[tid] += red[tid + s];
        __syncthreads();
    }
    float inv = 1.0f / red[0];
#pragma unroll
    for (int j = 0; j < 8; j++) e[j] *= inv;

    *(float4*)(row + base) = make_float4(e[0], e[1], e[2], e[3]);
    *(float4*)(row + base + 4) = make_float4(e[4], e[5], e[6], e[7]);

    if (base < keff) {
        ushort4 hh, ll;
        ushort_t h0, l0;
        split2(e[0], hh.x, ll.x); split2(e[1], hh.y, ll.y);
        split2(e[2], hh.z, ll.z); split2(e[3], hh.w, ll.w);
        *(ushort4*)(ph + r * (size_t)TT + base) = hh;
        *(ushort4*)(pl + r * (size_t)TT + base) = ll;
        split2(e[4], hh.x, ll.x); split2(e[5], hh.y, ll.y);
        split2(e[6], hh.z, ll.z); split2(e[7], hh.w, ll.w);
        *(ushort4*)(ph + r * (size_t)TT + base + 4) = hh;
        *(ushort4*)(pl + r * (size_t)TT + base + 4) = ll;
        (void)h0; (void)l0;
    }
}

// ---------------------------------------------------------------------------
extern "C" void kernel_launch(void* const* d_in, const int* in_sizes, int n_in,
                              void* d_out, int out_size)
{
    const float* x      = (const float*)d_in[0];
    const float* w_qkv  = (const float*)d_in[1];
    const float* w_proj = (const float*)d_in[2];
    float* out = (float*)d_out;

    ushort_t *xh, *xl, *wqkvh, *wqkvl, *wprojh, *wprojl, *qkvh, *qkvl;
    ushort_t *vth, *vtl, *ph, *pl, *ctxh, *ctxl;
    float *qkv, *ctx, *attn_fb;
    cudaGetSymbolAddress((void**)&xh, g_xh);
    cudaGetSymbolAddress((void**)&xl, g_xl);
    cudaGetSymbolAddress((void**)&wqkvh, g_wqkvh);
    cudaGetSymbolAddress((void**)&wqkvl, g_wqkvl);
    cudaGetSymbolAddress((void**)&wprojh, g_wprojh);
    cudaGetSymbolAddress((void**)&wprojl, g_wprojl);
    cudaGetSymbolAddress((void**)&qkv, g_qkv);
    cudaGetSymbolAddress((void**)&qkvh, g_qkvh);
    cudaGetSymbolAddress((void**)&qkvl, g_qkvl);
    cudaGetSymbolAddress((void**)&vth, g_vth);
    cudaGetSymbolAddress((void**)&vtl, g_vtl);
    cudaGetSymbolAddress((void**)&ph, g_ph);
    cudaGetSymbolAddress((void**)&pl, g_pl);
    cudaGetSymbolAddress((void**)&ctx, g_ctx);
    cudaGetSymbolAddress((void**)&ctxh, g_ctxh);
    cudaGetSymbolAddress((void**)&ctxl, g_ctxl);
    cudaGetSymbolAddress((void**)&attn_fb, g_attn_fallback);

    const size_t out_elems = (size_t)BB * TT * DM;
    float* attn = ((size_t)out_size > out_elems) ? (out + out_elems) : attn_fb;

    const int STAGE128 = 2 * 128 * 48 + 2 * 128 * 48;   // 24576
    const int STAGE64  = 2 * 128 * 48 + 2 * 64 * 48;    // 18432
    const int SMEM128 = 3 * STAGE128;                   // 73728
    const int SMEM64  = 3 * STAGE64;                    // 55296
    cudaFuncSetAttribute(gemm_mma<128, 0>, cudaFuncAttributeMaxDynamicSharedMemorySize, SMEM128);
    cudaFuncSetAttribute(gemm_mma<128, 1>, cudaFuncAttributeMaxDynamicSharedMemorySize, SMEM128);
    cudaFuncSetAttribute(gemm_mma<64, 2>,  cudaFuncAttributeMaxDynamicSharedMemorySize, SMEM64);

    const int M = BB * TT;   // 4096

    // 0) split inputs
    split_arr<<<M * DM / 4 / 256, 256>>>((const float4*)x, (ushort4*)xh, (ushort4*)xl, M * DM / 4);
    split_arr<<<3 * DM * DM / 4 / 256, 256>>>((const float4*)w_qkv, (ushort4*)wqkvh, (ushort4*)wqkvl, 3 * DM * DM / 4);
    split_arr<<<DM * DM / 4 / 256, 256>>>((const float4*)w_proj, (ushort4*)wprojh, (ushort4*)wprojl, DM * DM / 4);

    // 1) qkv = x @ w_qkv^T
    gemm_mma<128, 0><<<dim3(3 * DM / 128, M / 128, 1), 256, SMEM128>>>(
        xh, xl, wqkvh, wqkvl, qkv, DM, DM, DM, 3 * DM,
        0, 0, 0, 0, 0, 0, 1.0f);

    // 2) split qkv + transpose/split v
    split_arr<<<M * 3 * DM / 4 / 256, 256>>>((const float4*)qkv, (ushort4*)qkvh, (ushort4*)qkvl, M * 3 * DM / 4);
    transpose_v<<<dim3(DH / 32, TT / 32, BB * NH), dim3(32, 8)>>>(qkv, vth, vtl);

    // 3) scores = q @ k^T * 1/8, causal tile skip
    gemm_mma<128, 1><<<dim3(TT / 128, TT / 128, BB * NH), 256, SMEM128>>>(
        qkvh, qkvl, qkvh + DM, qkvl + DM, attn, DH, 3 * DM, 3 * DM, TT,
        (long long)TT * 3 * DM, DH,
        (long long)TT * 3 * DM, DH,
        (long long)NH * TT * TT, (long long)TT * TT, 0.125f);

    // 4) causal softmax + split probs
    softmax_split<<<BB * NH * TT, 256>>>(attn, ph, pl);

    // 5) ctx = P @ V (V^T as NT operand), causal K clamp
    gemm_mma<64, 2><<<dim3(1, TT / 128, BB * NH), 256, SMEM64>>>(
        ph, pl, vth, vtl, ctx, TT, TT, TT, DM,
        (long long)NH * TT * TT, (long long)TT * TT,
        (long long)NH * DH * TT, (long long)DH * TT,
        (long long)TT * DM, DH, 1.0f);

    // 6) split ctx, out = ctx @ w_proj^T
    split_arr<<<M * DM / 4 / 256, 256>>>((const float4*)ctx, (ushort4*)ctxh, (ushort4*)ctxl, M * DM / 4);
    gemm_mma<128, 0><<<dim3(DM / 128, M / 128, 1), 256, SMEM128>>>(
        ctxh, ctxl, wprojh, wprojl, out, DM, DM, DM, DM,
        0, 0, 0, 0, 0, 0, 1.0f);
}

// round 4
// speedup vs baseline: 1.7768x; 1.0204x over previous
#include <cuda_runtime.h>
#include <cuda_bf16.h>
#include <cstdint>
#include <math.h>

#define NH 16
#define DM 1024
#define DH 64
#define BB 2
#define TT 2048

typedef unsigned short ushort_t;

// ---------------------------------------------------------------------------
// Scratch (__device__ globals). Split: x ~= hi + lo (both bf16), separate arrays.
// ---------------------------------------------------------------------------
__device__ ushort_t g_xh[(size_t)BB * TT * DM];
__device__ ushort_t g_xl[(size_t)BB * TT * DM];
__device__ ushort_t g_wqkvh[(size_t)3 * DM * DM];
__device__ ushort_t g_wqkvl[(size_t)3 * DM * DM];
__device__ ushort_t g_wprojh[(size_t)DM * DM];
__device__ ushort_t g_wprojl[(size_t)DM * DM];
__device__ float    g_qkv[(size_t)BB * TT * 3 * DM];
__device__ ushort_t g_qkvh[(size_t)BB * TT * 3 * DM];
__device__ ushort_t g_qkvl[(size_t)BB * TT * 3 * DM];
__device__ ushort_t g_vth[(size_t)BB * NH * DH * TT];
__device__ ushort_t g_vtl[(size_t)BB * NH * DH * TT];
__device__ ushort_t g_ph[(size_t)BB * NH * TT * TT];
__device__ ushort_t g_pl[(size_t)BB * NH * TT * TT];
__device__ float    g_ctx[(size_t)BB * TT * DM];
__device__ ushort_t g_ctxh[(size_t)BB * TT * DM];
__device__ ushort_t g_ctxl[(size_t)BB * TT * DM];
__device__ float    g_attn_fallback[(size_t)BB * NH * TT * TT];

// ---------------------------------------------------------------------------
__device__ __forceinline__ uint32_t smem_u32(const void* p) {
    uint32_t a;
    asm("{ .reg .u64 t; cvta.to.shared.u64 t, %1; cvt.u32.u64 %0, t; }" : "=r"(a) : "l"(p));
    return a;
}
__device__ __forceinline__ void cp16(uint32_t dst, const void* src) {
    unsigned long long g = (unsigned long long)__cvta_generic_to_global(src);
    asm volatile("cp.async.cg.shared.global [%0], [%1], 16;" :: "r"(dst), "l"(g));
}
#define CP_COMMIT() asm volatile("cp.async.commit_group;" ::: "memory")
#define CP_WAIT1()  asm volatile("cp.async.wait_group 1;" ::: "memory")
#define CP_WAIT2()  asm volatile("cp.async.wait_group 2;" ::: "memory")

__device__ __forceinline__ void ldsm4(uint32_t* r, uint32_t addr) {
    asm volatile("ldmatrix.sync.aligned.m8n8.x4.shared.b16 {%0,%1,%2,%3}, [%4];"
        : "=r"(r[0]), "=r"(r[1]), "=r"(r[2]), "=r"(r[3]) : "r"(addr));
}
__device__ __forceinline__ void mma16816(float* c, const uint32_t* a, uint32_t b0, uint32_t b1) {
    asm volatile("mma.sync.aligned.m16n8k16.row.col.f32.bf16.bf16.f32 "
        "{%0,%1,%2,%3}, {%4,%5,%6,%7}, {%8,%9}, {%0,%1,%2,%3};"
        : "+f"(c[0]), "+f"(c[1]), "+f"(c[2]), "+f"(c[3])
        : "r"(a[0]), "r"(a[1]), "r"(a[2]), "r"(a[3]), "r"(b0), "r"(b1));
}
__device__ __forceinline__ void split2(float x, ushort_t& h, ushort_t& l) {
    __nv_bfloat16 hb = __float2bfloat16(x);
    float hf = __bfloat162float(hb);
    __nv_bfloat16 lb = __float2bfloat16(x - hf);
    h = __bfloat16_as_ushort(hb);
    l = __bfloat16_as_ushort(lb);
}

// ---------------------------------------------------------------------------
__global__ __launch_bounds__(256) void split_arr(const float4* __restrict__ in,
                                                 ushort4* __restrict__ hi,
                                                 ushort4* __restrict__ lo, int n4) {
    int i = blockIdx.x * 256 + threadIdx.x;
    if (i < n4) {
        float4 v = in[i];
        ushort4 h, l;
        split2(v.x, h.x, l.x); split2(v.y, h.y, l.y);
        split2(v.z, h.z, l.z); split2(v.w, h.w, l.w);
        hi[i] = h; lo[i] = l;
    }
}

__global__ __launch_bounds__(256) void transpose_v(const float* __restrict__ qkv,
                                                   ushort_t* __restrict__ vth,
                                                   ushort_t* __restrict__ vtl) {
    __shared__ uint32_t tile[32][33];
    int bh = blockIdx.z;
    int b = bh >> 4, h = bh & 15;
    int t0 = blockIdx.y * 32, d0 = blockIdx.x * 32;
    int tx = threadIdx.x, ty = threadIdx.y;
#pragma unroll
    for (int j = 0; j < 4; j++) {
        int t = t0 + ty + j * 8;
        int d = d0 + tx;
        ushort_t hh, ll;
        split2(qkv[((size_t)b * TT + t) * (3 * DM) + 2 * DM + h * DH + d], hh, ll);
        tile[ty + j * 8][tx] = (uint32_t)hh | ((uint32_t)ll << 16);
    }
    __syncthreads();
#pragma unroll
    for (int j = 0; j < 4; j++) {
        int d = d0 + ty + j * 8;
        int t = t0 + tx;
        uint32_t v = tile[tx][ty + j * 8];
        size_t idx = ((size_t)bh * DH + d) * TT + t;
        vth[idx] = (ushort_t)(v & 0xFFFF);
        vtl[idx] = (ushort_t)(v >> 16);
    }
}

// ---------------------------------------------------------------------------
// Split-bf16 mma.sync GEMM v2: KC=32, 3-stage cp.async, XOR-swizzled smem.
// C[M,N] = alpha * A[M,K] * B[N,K]^T. BM=128, BN in {64,128}. 8 warps.
// CMODE: 0 none, 2 causal K clamp. Rows: 64B data, swz c' = c ^ ((r>>1)&3).
// ---------------------------------------------------------------------------
template <int BN, int CMODE>
__global__ __launch_bounds__(256) void gemm_mma2(
    const ushort_t* __restrict__ Ahp, const ushort_t* __restrict__ Alp,
    const ushort_t* __restrict__ Bhp, const ushort_t* __restrict__ Blp,
    float* __restrict__ C,
    int K, int lda, int ldb, int ldc,
    long long sAb, long long sAh, long long sBb, long long sBh,
    long long sCb, long long sCh, float alpha)
{
    constexpr int NP = BN / 32;
    constexpr int A_BYTES = 128 * 64;
    constexpr int B_BYTES = BN * 64;
    constexpr int STAGE = 2 * A_BYTES + 2 * B_BYTES;
    constexpr int OFF_AH = 0, OFF_AL = A_BYTES, OFF_BH = 2 * A_BYTES, OFF_BL = 2 * A_BYTES + B_BYTES;
    constexpr int NBJ = (BN * 4) / 256;      // B chunks per thread

    int bx = blockIdx.x, by = blockIdx.y, bz = blockIdx.z;
    int row0 = by * 128, col0 = bx * BN;

    int b = bz >> 4, h = bz & 15;
    Ahp += (size_t)b * sAb + (size_t)h * sAh;
    Alp += (size_t)b * sAb + (size_t)h * sAh;
    Bhp += (size_t)b * sBb + (size_t)h * sBh;
    Blp += (size_t)b * sBb + (size_t)h * sBh;
    C   += (size_t)b * sCb + (size_t)h * sCh;

    extern __shared__ char smraw[];
    uint32_t smb = smem_u32(smraw);

    int tid = threadIdx.x;
    int wid = tid >> 5, L = tid & 31;
    int warp_row = (wid & 3) * 32;
    int warp_col = (wid >> 2) * (BN / 2);

    int Keff = (CMODE == 2) ? min(K, row0 + 128) : K;
    int nc = Keff >> 5;

    int ldrow = ((L >> 3) & 1) * 8 + (L & 7);
    int ldk   = L >> 4;                       // chunk half within k16

    float acc[2][2 * NP][4];
#pragma unroll
    for (int i = 0; i < 2; i++)
#pragma unroll
        for (int j = 0; j < 2 * NP; j++)
#pragma unroll
            for (int q = 0; q < 4; q++) acc[i][j][q] = 0.f;

    // loader: stage sb, global k offset k0 (elements)
    auto load_stage = [&](uint32_t sb, int k0) {
#pragma unroll
        for (int j = 0; j < 2; j++) {
            int slot = tid * 2 + j;
            int r = slot >> 2, c = slot & 3;
            uint32_t d = (uint32_t)(r * 64 + ((c ^ ((r >> 1) & 3)) * 16));
            const ushort_t* sh = Ahp + (size_t)(row0 + r) * lda + k0 + c * 8;
            const ushort_t* sl = Alp + (size_t)(row0 + r) * lda + k0 + c * 8;
            cp16(sb + OFF_AH + d, sh);
            cp16(sb + OFF_AL + d, sl);
        }
#pragma unroll
        for (int j = 0; j < NBJ; j++) {
            int slot = tid * NBJ + j;
            int r = slot >> 2, c = slot & 3;
            uint32_t d = (uint32_t)(r * 64 + ((c ^ ((r >> 1) & 3)) * 16));
            const ushort_t* sh = Bhp + (size_t)(col0 + r) * ldb + k0 + c * 8;
            const ushort_t* sl = Blp + (size_t)(col0 + r) * ldb + k0 + c * 8;
            cp16(sb + OFF_BH + d, sh);
            cp16(sb + OFF_BL + d, sl);
        }
    };

#pragma unroll
    for (int s = 0; s < 2; s++) {
        if (s < nc) load_stage(smb + s * STAGE, s * 32);
        CP_COMMIT();
    }

    for (int ch = 0; ch < nc; ch++) {
        int sN = ch + 2;
        if (sN < nc) load_stage(smb + (sN % 3) * STAGE, sN * 32);
        CP_COMMIT();
        CP_WAIT2();
        __syncthreads();

        uint32_t sb = smb + (ch % 3) * STAGE;
#pragma unroll
        for (int s = 0; s < 2; s++) {
            int cbase = 2 * s + ldk;
            uint32_t ah[2][4], al[2][4];
#pragma unroll
            for (int mt = 0; mt < 2; mt++) {
                int rr = warp_row + mt * 16 + ldrow;
                uint32_t ra = (uint32_t)(rr * 64 + ((cbase ^ ((rr >> 1) & 3)) * 16));
                ldsm4(ah[mt], sb + OFF_AH + ra);
                ldsm4(al[mt], sb + OFF_AL + ra);
            }
#pragma unroll
            for (int np = 0; np < NP; np++) {
                int rr = warp_col + np * 16 + ldrow;
                uint32_t rb = (uint32_t)(rr * 64 + ((cbase ^ ((rr >> 1) & 3)) * 16));
                uint32_t bh[4], bl[4];
                ldsm4(bh, sb + OFF_BH + rb);
                ldsm4(bl, sb + OFF_BL + rb);
#pragma unroll
                for (int mt = 0; mt < 2; mt++) {
                    mma16816(acc[mt][2 * np],     ah[mt], bh[0], bh[2]);
                    mma16816(acc[mt][2 * np],     ah[mt], bl[0], bl[2]);
                    mma16816(acc[mt][2 * np],     al[mt], bh[0], bh[2]);
                    mma16816(acc[mt][2 * np + 1], ah[mt], bh[1], bh[3]);
                    mma16816(acc[mt][2 * np + 1], ah[mt], bl[1], bl[3]);
                    mma16816(acc[mt][2 * np + 1], al[mt], bh[1], bh[3]);
                }
            }
        }
        __syncthreads();
    }

#pragma unroll
    for (int mt = 0; mt < 2; mt++) {
        int r0g = row0 + warp_row + mt * 16 + (L >> 2);
#pragma unroll
        for (int nt = 0; nt < 2 * NP; nt++) {
            int cg = col0 + warp_col + nt * 8 + (L & 3) * 2;
            float* p0 = C + (size_t)r0g * ldc + cg;
            float* p1 = C + (size_t)(r0g + 8) * ldc + cg;
            *(float2*)p0 = make_float2(alpha * acc[mt][nt][0], alpha * acc[mt][nt][1]);
            *(float2*)p1 = make_float2(alpha * acc[mt][nt][2], alpha * acc[mt][nt][3]);
        }
    }
}

// ---------------------------------------------------------------------------
// Scores kernel: per-CTA Q tile (128 x 64) persistent in smem; loops over the
// causal row of K tiles with depth-1 cp.async prefetch. Writes attn tile * 1/8.
// Rows = 128B (64 bf16); swz c' = c ^ (r&7).
// grid: (16, 1, BB*NH); by = 15 - blockIdx.x (longest rows first).
// ---------------------------------------------------------------------------
__global__ __launch_bounds__(256) void scores_mma(
    const ushort_t* __restrict__ qkvh, const ushort_t* __restrict__ qkvl,
    float* __restrict__ attn)
{
    constexpr int QH = 0, QL = 16384;
    constexpr int KST = 32768;               // K stages base
    constexpr int KSTG = 32768;              // per stage: KH 16KB + KL 16KB
    constexpr int KLOFF = 16384;
    const int ldq = 3 * DM;

    int by = 15 - blockIdx.x;
    int bh = blockIdx.z;
    int b = bh >> 4, h = bh & 15;
    int row0 = by * 128;

    const ushort_t* Qh = qkvh + (size_t)b * TT * 3 * DM + h * DH;
    const ushort_t* Ql = qkvl + (size_t)b * TT * 3 * DM + h * DH;
    const ushort_t* Kh = Qh + DM;
    const ushort_t* Kl = Ql + DM;
    float* Cb = attn + (size_t)bh * TT * TT;

    extern __shared__ char smraw[];
    uint32_t smb = smem_u32(smraw);

    int tid = threadIdx.x;
    int wid = tid >> 5, L = tid & 31;
    int warp_row = (wid & 3) * 32;
    int warp_col = (wid >> 2) * 64;
    int ldrow = ((L >> 3) & 1) * 8 + (L & 7);
    int ldk   = L >> 4;

    int lrow = tid >> 1;                      // load row
    int lc0  = (tid & 1) * 4;                 // chunk base (4 chunks)

    // prologue: Q + K0 (group 0)
#pragma unroll
    for (int j = 0; j < 4; j++) {
        int c = lc0 + j;
        uint32_t d = (uint32_t)(lrow * 128 + ((c ^ (lrow & 7)) * 16));
        cp16(smb + QH + d, Qh + (size_t)(row0 + lrow) * ldq + c * 8);
        cp16(smb + QL + d, Ql + (size_t)(row0 + lrow) * ldq + c * 8);
        cp16(smb + KST + d, Kh + (size_t)lrow * ldq + c * 8);
        cp16(smb + KST + KLOFF + d, Kl + (size_t)lrow * ldq + c * 8);
    }
    CP_COMMIT();

    for (int jt = 0; jt <= by; jt++) {
        if (jt + 1 <= by) {
            uint32_t sb = smb + KST + ((jt + 1) & 1) * KSTG;
#pragma unroll
            for (int j = 0; j < 4; j++) {
                int c = lc0 + j;
                uint32_t d = (uint32_t)(lrow * 128 + ((c ^ (lrow & 7)) * 16));
                cp16(sb + d, Kh + (size_t)((jt + 1) * 128 + lrow) * ldq + c * 8);
                cp16(sb + KLOFF + d, Kl + (size_t)((jt + 1) * 128 + lrow) * ldq + c * 8);
            }
        }
        CP_COMMIT();
        CP_WAIT1();
        __syncthreads();

        float acc[2][8][4];
#pragma unroll
        for (int i = 0; i < 2; i++)
#pragma unroll
            for (int j = 0; j < 8; j++)
#pragma unroll
                for (int q = 0; q < 4; q++) acc[i][j][q] = 0.f;

        uint32_t kb = smb + KST + (jt & 1) * KSTG;
#pragma unroll
        for (int s = 0; s < 4; s++) {
            int cbase = 2 * s + ldk;
            uint32_t ah[2][4], al[2][4];
#pragma unroll
            for (int mt = 0; mt < 2; mt++) {
                int rr = warp_row + mt * 16 + ldrow;
                uint32_t ra = (uint32_t)(rr * 128 + ((cbase ^ (rr & 7)) * 16));
                ldsm4(ah[mt], smb + QH + ra);
                ldsm4(al[mt], smb + QL + ra);
            }
#pragma unroll
            for (int np = 0; np < 4; np++) {
                int rr = warp_col + np * 16 + ldrow;
                uint32_t rb = (uint32_t)(rr * 128 + ((cbase ^ (rr & 7)) * 16));
                uint32_t bh4[4], bl4[4];
                ldsm4(bh4, kb + rb);
                ldsm4(bl4, kb + KLOFF + rb);
#pragma unroll
                for (int mt = 0; mt < 2; mt++) {
                    mma16816(acc[mt][2 * np],     ah[mt], bh4[0], bh4[2]);
                    mma16816(acc[mt][2 * np],     ah[mt], bl4[0], bl4[2]);
                    mma16816(acc[mt][2 * np],     al[mt], bh4[0], bh4[2]);
                    mma16816(acc[mt][2 * np + 1], ah[mt], bh4[1], bh4[3]);
                    mma16816(acc[mt][2 * np + 1], ah[mt], bl4[1], bl4[3]);
                    mma16816(acc[mt][2 * np + 1], al[mt], bh4[1], bh4[3]);
                }
            }
        }

        int col0 = jt * 128;
#pragma unroll
        for (int mt = 0; mt < 2; mt++) {
            int r0g = row0 + warp_row + mt * 16 + (L >> 2);
#pragma unroll
            for (int nt = 0; nt < 8; nt++) {
                int cg = col0 + warp_col + nt * 8 + (L & 3) * 2;
                float* p0 = Cb + (size_t)r0g * TT + cg;
                float* p1 = Cb + (size_t)(r0g + 8) * TT + cg;
                *(float2*)p0 = make_float2(0.125f * acc[mt][nt][0], 0.125f * acc[mt][nt][1]);
                *(float2*)p1 = make_float2(0.125f * acc[mt][nt][2], 0.125f * acc[mt][nt][3]);
            }
        }
        __syncthreads();
    }
}

// ---------------------------------------------------------------------------
// Causal softmax: reads only valid (128-rounded) prefix; writes fp32 row
// (exact zeros in tail) + split-bf16 probs for the valid prefix.
// ---------------------------------------------------------------------------
__global__ __launch_bounds__(256) void softmax_split(float* __restrict__ attn,
                                                     ushort_t* __restrict__ ph,
                                                     ushort_t* __restrict__ pl) {
    __shared__ float red[256];
    size_t r = blockIdx.x;
    int q = (int)(r & (TT - 1));
    int len = q + 1;
    int keff = ((q >> 7) << 7) + 128;
    float* row = attn + r * (size_t)TT;
    int tid = threadIdx.x;
    int base = tid * 8;
    bool act = base < keff;

    float vals[8];
    if (act) {
        float4 v0 = *(const float4*)(row + base);
        float4 v1 = *(const float4*)(row + base + 4);
        vals[0] = v0.x; vals[1] = v0.y; vals[2] = v0.z; vals[3] = v0.w;
        vals[4] = v1.x; vals[5] = v1.y; vals[6] = v1.z; vals[7] = v1.w;
    }

    float m = -INFINITY;
    if (act) {
#pragma unroll
        for (int j = 0; j < 8; j++) if (base + j < len) m = fmaxf(m, vals[j]);
    }
    red[tid] = m; __syncthreads();
#pragma unroll
    for (int s = 128; s > 0; s >>= 1) {
        if (tid < s) red[tid] = fmaxf(red[tid], red[tid + s]);
        __syncthreads();
    }
    m = red[0]; __syncthreads();

    float e[8]; float sum = 0.f;
#pragma unroll
    for (int j = 0; j < 8; j++) {
        e[j] = (act && base + j < len) ? __expf(vals[j] - m) : 0.f;
        sum += e[j];
    }
    red[tid] = sum; __syncthreads();
#pragma unroll
    for (int s = 128; s > 0; s >>= 1) {
        if (tid < s) red[tid] += red[tid + s];
        __syncthreads();
    }
    float inv = 1.0f / red[0];
#pragma unroll
    for (int j = 0; j < 8; j++) e[j] *= inv;

    *(float4*)(row + base) = make_float4(e[0], e[1], e[2], e[3]);
    *(float4*)(row + base + 4) = make_float4(e[4], e[5], e[6], e[7]);

    if (act) {
        ushort4 hh, ll;
        split2(e[0], hh.x, ll.x); split2(e[1], hh.y, ll.y);
        split2(e[2], hh.z, ll.z); split2(e[3], hh.w, ll.w);
        *(ushort4*)(ph + r * (size_t)TT + base) = hh;
        *(ushort4*)(pl + r * (size_t)TT + base) = ll;
        split2(e[4], hh.x, ll.x); split2(e[5], hh.y, ll.y);
        split2(e[6], hh.z, ll.z); split2(e[7], hh.w, ll.w);
        *(ushort4*)(ph + r * (size_t)TT + base + 4) = hh;
        *(ushort4*)(pl + r * (size_t)TT + base + 4) = ll;
    }
}

// ---------------------------------------------------------------------------
extern "C" void kernel_launch(void* const* d_in, const int* in_sizes, int n_in,
                              void* d_out, int out_size)
{
    const float* x      = (const float*)d_in[0];
    const float* w_qkv  = (const float*)d_in[1];
    const float* w_proj = (const float*)d_in[2];
    float* out = (float*)d_out;

    ushort_t *xh, *xl, *wqkvh, *wqkvl, *wprojh, *wprojl, *qkvh, *qkvl;
    ushort_t *vth, *vtl, *ph, *pl, *ctxh, *ctxl;
    float *qkv, *ctx, *attn_fb;
    cudaGetSymbolAddress((void**)&xh, g_xh);
    cudaGetSymbolAddress((void**)&xl, g_xl);
    cudaGetSymbolAddress((void**)&wqkvh, g_wqkvh);
    cudaGetSymbolAddress((void**)&wqkvl, g_wqkvl);
    cudaGetSymbolAddress((void**)&wprojh, g_wprojh);
    cudaGetSymbolAddress((void**)&wprojl, g_wprojl);
    cudaGetSymbolAddress((void**)&qkv, g_qkv);
    cudaGetSymbolAddress((void**)&qkvh, g_qkvh);
    cudaGetSymbolAddress((void**)&qkvl, g_qkvl);
    cudaGetSymbolAddress((void**)&vth, g_vth);
    cudaGetSymbolAddress((void**)&vtl, g_vtl);
    cudaGetSymbolAddress((void**)&ph, g_ph);
    cudaGetSymbolAddress((void**)&pl, g_pl);
    cudaGetSymbolAddress((void**)&ctx, g_ctx);
    cudaGetSymbolAddress((void**)&ctxh, g_ctxh);
    cudaGetSymbolAddress((void**)&ctxl, g_ctxl);
    cudaGetSymbolAddress((void**)&attn_fb, g_attn_fallback);

    const size_t out_elems = (size_t)BB * TT * DM;
    float* attn = ((size_t)out_size > out_elems) ? (out + out_elems) : attn_fb;

    const int SMEM128 = 3 * (2 * 128 * 64 + 2 * 128 * 64);  // 98304
    const int SMEM64  = 3 * (2 * 128 * 64 + 2 * 64 * 64);   // 73728
    const int SMEMSC  = 32768 + 2 * 32768;                  // 98304
    cudaFuncSetAttribute(gemm_mma2<128, 0>, cudaFuncAttributeMaxDynamicSharedMemorySize, SMEM128);
    cudaFuncSetAttribute(gemm_mma2<64, 2>,  cudaFuncAttributeMaxDynamicSharedMemorySize, SMEM64);
    cudaFuncSetAttribute(scores_mma, cudaFuncAttributeMaxDynamicSharedMemorySize, SMEMSC);

    const int M = BB * TT;

    // 0) split inputs
    split_arr<<<M * DM / 4 / 256, 256>>>((const float4*)x, (ushort4*)xh, (ushort4*)xl, M * DM / 4);
    split_arr<<<3 * DM * DM / 4 / 256, 256>>>((const float4*)w_qkv, (ushort4*)wqkvh, (ushort4*)wqkvl, 3 * DM * DM / 4);
    split_arr<<<DM * DM / 4 / 256, 256>>>((const float4*)w_proj, (ushort4*)wprojh, (ushort4*)wprojl, DM * DM / 4);

    // 1) qkv = x @ w_qkv^T
    gemm_mma2<128, 0><<<dim3(3 * DM / 128, M / 128, 1), 256, SMEM128>>>(
        xh, xl, wqkvh, wqkvl, qkv, DM, DM, DM, 3 * DM,
        0, 0, 0, 0, 0, 0, 1.0f);

    // 2) split qkv + transpose/split v
    split_arr<<<M * 3 * DM / 4 / 256, 256>>>((const float4*)qkv, (ushort4*)qkvh, (ushort4*)qkvl, M * 3 * DM / 4);
    transpose_v<<<dim3(DH / 32, TT / 32, BB * NH), dim3(32, 8)>>>(qkv, vth, vtl);

    // 3) scores (fused Q-tile reuse, causal)
    scores_mma<<<dim3(16, 1, BB * NH), 256, SMEMSC>>>(qkvh, qkvl, attn);

    // 4) causal softmax + split probs
    softmax_split<<<BB * NH * TT, 256>>>(attn, ph, pl);

    // 5) ctx = P @ V (V^T as NT operand), causal K clamp
    gemm_mma2<64, 2><<<dim3(1, TT / 128, BB * NH), 256, SMEM64>>>(
        ph, pl, vth, vtl, ctx, TT, TT, TT, DM,
        (long long)NH * TT * TT, (long long)TT * TT,
        (long long)NH * DH * TT, (long long)DH * TT,
        (long long)TT * DM, DH, 1.0f);

    // 6) split ctx, out = ctx @ w_proj^T
    split_arr<<<M * DM / 4 / 256, 256>>>((const float4*)ctx, (ushort4*)ctxh, (ushort4*)ctxl, M * DM / 4);
    gemm_mma2<128, 0><<<dim3(DM / 128, M / 128, 1), 256, SMEM128>>>(
        ctxh, ctxl, wprojh, wprojl, out, DM, DM, DM, DM,
        0, 0, 0, 0, 0, 0, 1.0f);
}

// round 5
// speedup vs baseline: 1.7785x; 1.0009x over previous
#include <cuda_runtime.h>
#include <cuda_bf16.h>
#include <cstdint>
#include <math.h>

#define NH 16
#define DM 1024
#define DH 64
#define BB 2
#define TT 2048

typedef unsigned short ushort_t;

// ---------------------------------------------------------------------------
__device__ ushort_t g_xh[(size_t)BB * TT * DM];
__device__ ushort_t g_xl[(size_t)BB * TT * DM];
__device__ ushort_t g_wqkvh[(size_t)3 * DM * DM];
__device__ ushort_t g_wqkvl[(size_t)3 * DM * DM];
__device__ ushort_t g_wprojh[(size_t)DM * DM];
__device__ ushort_t g_wprojl[(size_t)DM * DM];
__device__ float    g_qkv[(size_t)BB * TT * 3 * DM];
__device__ ushort_t g_qkvh[(size_t)BB * TT * 3 * DM];
__device__ ushort_t g_qkvl[(size_t)BB * TT * 3 * DM];
__device__ ushort_t g_vth[(size_t)BB * NH * DH * TT];
__device__ ushort_t g_vtl[(size_t)BB * NH * DH * TT];
__device__ ushort_t g_ph[(size_t)BB * NH * TT * TT];
__device__ ushort_t g_pl[(size_t)BB * NH * TT * TT];
__device__ float    g_ctx[(size_t)BB * TT * DM];
__device__ ushort_t g_ctxh[(size_t)BB * TT * DM];
__device__ ushort_t g_ctxl[(size_t)BB * TT * DM];
__device__ float    g_attn_fallback[(size_t)BB * NH * TT * TT];

// ---------------------------------------------------------------------------
__device__ __forceinline__ uint32_t smem_u32(const void* p) {
    uint32_t a;
    asm("{ .reg .u64 t; cvta.to.shared.u64 t, %1; cvt.u32.u64 %0, t; }" : "=r"(a) : "l"(p));
    return a;
}
__device__ __forceinline__ void cp16(uint32_t dst, const void* src) {
    unsigned long long g = (unsigned long long)__cvta_generic_to_global(src);
    asm volatile("cp.async.cg.shared.global [%0], [%1], 16;" :: "r"(dst), "l"(g));
}
#define CP_COMMIT() asm volatile("cp.async.commit_group;" ::: "memory")
#define CP_WAIT1()  asm volatile("cp.async.wait_group 1;" ::: "memory")
#define CP_WAIT2()  asm volatile("cp.async.wait_group 2;" ::: "memory")

__device__ __forceinline__ void ldsm4(uint32_t* r, uint32_t addr) {
    asm volatile("ldmatrix.sync.aligned.m8n8.x4.shared.b16 {%0,%1,%2,%3}, [%4];"
        : "=r"(r[0]), "=r"(r[1]), "=r"(r[2]), "=r"(r[3]) : "r"(addr));
}
__device__ __forceinline__ void mma16816(float* c, const uint32_t* a, uint32_t b0, uint32_t b1) {
    asm volatile("mma.sync.aligned.m16n8k16.row.col.f32.bf16.bf16.f32 "
        "{%0,%1,%2,%3}, {%4,%5,%6,%7}, {%8,%9}, {%0,%1,%2,%3};"
        : "+f"(c[0]), "+f"(c[1]), "+f"(c[2]), "+f"(c[3])
        : "r"(a[0]), "r"(a[1]), "r"(a[2]), "r"(a[3]), "r"(b0), "r"(b1));
}
__device__ __forceinline__ void split2(float x, ushort_t& h, ushort_t& l) {
    __nv_bfloat16 hb = __float2bfloat16(x);
    float hf = __bfloat162float(hb);
    __nv_bfloat16 lb = __float2bfloat16(x - hf);
    h = __bfloat16_as_ushort(hb);
    l = __bfloat16_as_ushort(lb);
}

// ---------------------------------------------------------------------------
__global__ __launch_bounds__(256) void split_arr(const float4* __restrict__ in,
                                                 ushort4* __restrict__ hi,
                                                 ushort4* __restrict__ lo, int n4) {
    int i = blockIdx.x * 256 + threadIdx.x;
    if (i < n4) {
        float4 v = in[i];
        ushort4 h, l;
        split2(v.x, h.x, l.x); split2(v.y, h.y, l.y);
        split2(v.z, h.z, l.z); split2(v.w, h.w, l.w);
        hi[i] = h; lo[i] = l;
    }
}

__global__ __launch_bounds__(256) void transpose_v(const float* __restrict__ qkv,
                                                   ushort_t* __restrict__ vth,
                                                   ushort_t* __restrict__ vtl) {
    __shared__ uint32_t tile[32][33];
    int bh = blockIdx.z;
    int b = bh >> 4, h = bh & 15;
    int t0 = blockIdx.y * 32, d0 = blockIdx.x * 32;
    int tx = threadIdx.x, ty = threadIdx.y;
#pragma unroll
    for (int j = 0; j < 4; j++) {
        int t = t0 + ty + j * 8;
        int d = d0 + tx;
        ushort_t hh, ll;
        split2(qkv[((size_t)b * TT + t) * (3 * DM) + 2 * DM + h * DH + d], hh, ll);
        tile[ty + j * 8][tx] = (uint32_t)hh | ((uint32_t)ll << 16);
    }
    __syncthreads();
#pragma unroll
    for (int j = 0; j < 4; j++) {
        int d = d0 + ty + j * 8;
        int t = t0 + tx;
        uint32_t v = tile[tx][ty + j * 8];
        size_t idx = ((size_t)bh * DH + d) * TT + t;
        vth[idx] = (ushort_t)(v & 0xFFFF);
        vtl[idx] = (ushort_t)(v >> 16);
    }
}

// ---------------------------------------------------------------------------
// Split-bf16 mma.sync GEMM: KC=32, 3-stage cp.async, XOR-swizzled smem.
// MMA issue order: per split-term sweeps over 4 accumulators (dep distance 4).
// ---------------------------------------------------------------------------
template <int BN, int CMODE>
__global__ __launch_bounds__(256) void gemm_mma2(
    const ushort_t* __restrict__ Ahp, const ushort_t* __restrict__ Alp,
    const ushort_t* __restrict__ Bhp, const ushort_t* __restrict__ Blp,
    float* __restrict__ C,
    int K, int lda, int ldb, int ldc,
    long long sAb, long long sAh, long long sBb, long long sBh,
    long long sCb, long long sCh, float alpha)
{
    constexpr int NP = BN / 32;
    constexpr int A_BYTES = 128 * 64;
    constexpr int B_BYTES = BN * 64;
    constexpr int STAGE = 2 * A_BYTES + 2 * B_BYTES;
    constexpr int OFF_AH = 0, OFF_AL = A_BYTES, OFF_BH = 2 * A_BYTES, OFF_BL = 2 * A_BYTES + B_BYTES;
    constexpr int NBJ = (BN * 4) / 256;

    int bx = blockIdx.x, by = blockIdx.y, bz = blockIdx.z;
    int row0 = by * 128, col0 = bx * BN;

    int b = bz >> 4, h = bz & 15;
    Ahp += (size_t)b * sAb + (size_t)h * sAh;
    Alp += (size_t)b * sAb + (size_t)h * sAh;
    Bhp += (size_t)b * sBb + (size_t)h * sBh;
    Blp += (size_t)b * sBb + (size_t)h * sBh;
    C   += (size_t)b * sCb + (size_t)h * sCh;

    extern __shared__ char smraw[];
    uint32_t smb = smem_u32(smraw);

    int tid = threadIdx.x;
    int wid = tid >> 5, L = tid & 31;
    int warp_row = (wid & 3) * 32;
    int warp_col = (wid >> 2) * (BN / 2);

    int Keff = (CMODE == 2) ? min(K, row0 + 128) : K;
    int nc = Keff >> 5;

    int ldrow = ((L >> 3) & 1) * 8 + (L & 7);
    int ldk   = L >> 4;

    float acc[2][2 * NP][4];
#pragma unroll
    for (int i = 0; i < 2; i++)
#pragma unroll
        for (int j = 0; j < 2 * NP; j++)
#pragma unroll
            for (int q = 0; q < 4; q++) acc[i][j][q] = 0.f;

    auto load_stage = [&](uint32_t sb, int k0) {
#pragma unroll
        for (int j = 0; j < 2; j++) {
            int slot = tid * 2 + j;
            int r = slot >> 2, c = slot & 3;
            uint32_t d = (uint32_t)(r * 64 + ((c ^ ((r >> 1) & 3)) * 16));
            cp16(sb + OFF_AH + d, Ahp + (size_t)(row0 + r) * lda + k0 + c * 8);
            cp16(sb + OFF_AL + d, Alp + (size_t)(row0 + r) * lda + k0 + c * 8);
        }
#pragma unroll
        for (int j = 0; j < NBJ; j++) {
            int slot = tid * NBJ + j;
            int r = slot >> 2, c = slot & 3;
            uint32_t d = (uint32_t)(r * 64 + ((c ^ ((r >> 1) & 3)) * 16));
            cp16(sb + OFF_BH + d, Bhp + (size_t)(col0 + r) * ldb + k0 + c * 8);
            cp16(sb + OFF_BL + d, Blp + (size_t)(col0 + r) * ldb + k0 + c * 8);
        }
    };

#pragma unroll
    for (int s = 0; s < 2; s++) {
        if (s < nc) load_stage(smb + s * STAGE, s * 32);
        CP_COMMIT();
    }

    for (int ch = 0; ch < nc; ch++) {
        int sN = ch + 2;
        if (sN < nc) load_stage(smb + (sN % 3) * STAGE, sN * 32);
        CP_COMMIT();
        CP_WAIT2();
        __syncthreads();

        uint32_t sb = smb + (ch % 3) * STAGE;
#pragma unroll
        for (int s = 0; s < 2; s++) {
            int cbase = 2 * s + ldk;
            uint32_t ah[2][4], al[2][4];
#pragma unroll
            for (int mt = 0; mt < 2; mt++) {
                int rr = warp_row + mt * 16 + ldrow;
                uint32_t ra = (uint32_t)(rr * 64 + ((cbase ^ ((rr >> 1) & 3)) * 16));
                ldsm4(ah[mt], sb + OFF_AH + ra);
                ldsm4(al[mt], sb + OFF_AL + ra);
            }
#pragma unroll
            for (int np = 0; np < NP; np++) {
                int rr = warp_col + np * 16 + ldrow;
                uint32_t rb = (uint32_t)(rr * 64 + ((cbase ^ ((rr >> 1) & 3)) * 16));
                uint32_t bh[4], bl[4];
                ldsm4(bh, sb + OFF_BH + rb);
                ldsm4(bl, sb + OFF_BL + rb);
                // term sweeps: same-acc reuse distance = 4
#pragma unroll
                for (int mt = 0; mt < 2; mt++) {
                    mma16816(acc[mt][2 * np],     ah[mt], bh[0], bh[2]);
                    mma16816(acc[mt][2 * np + 1], ah[mt], bh[1], bh[3]);
                }
#pragma unroll
                for (int mt = 0; mt < 2; mt++) {
                    mma16816(acc[mt][2 * np],     ah[mt], bl[0], bl[2]);
                    mma16816(acc[mt][2 * np + 1], ah[mt], bl[1], bl[3]);
                }
#pragma unroll
                for (int mt = 0; mt < 2; mt++) {
                    mma16816(acc[mt][2 * np],     al[mt], bh[0], bh[2]);
                    mma16816(acc[mt][2 * np + 1], al[mt], bh[1], bh[3]);
                }
            }
        }
        __syncthreads();
    }

#pragma unroll
    for (int mt = 0; mt < 2; mt++) {
        int r0g = row0 + warp_row + mt * 16 + (L >> 2);
#pragma unroll
        for (int nt = 0; nt < 2 * NP; nt++) {
            int cg = col0 + warp_col + nt * 8 + (L & 3) * 2;
            float* p0 = C + (size_t)r0g * ldc + cg;
            float* p1 = C + (size_t)(r0g + 8) * ldc + cg;
            *(float2*)p0 = make_float2(alpha * acc[mt][nt][0], alpha * acc[mt][nt][1]);
            *(float2*)p1 = make_float2(alpha * acc[mt][nt][2], alpha * acc[mt][nt][3]);
        }
    }
}

// ---------------------------------------------------------------------------
// Scores kernel: persistent Q tile, causal row sweep, term-sweep MMA order.
// ---------------------------------------------------------------------------
__global__ __launch_bounds__(256) void scores_mma(
    const ushort_t* __restrict__ qkvh, const ushort_t* __restrict__ qkvl,
    float* __restrict__ attn)
{
    constexpr int QH = 0, QL = 16384;
    constexpr int KST = 32768;
    constexpr int KSTG = 32768;
    constexpr int KLOFF = 16384;
    const int ldq = 3 * DM;

    int by = 15 - blockIdx.x;
    int bh = blockIdx.z;
    int b = bh >> 4, h = bh & 15;
    int row0 = by * 128;

    const ushort_t* Qh = qkvh + (size_t)b * TT * 3 * DM + h * DH;
    const ushort_t* Ql = qkvl + (size_t)b * TT * 3 * DM + h * DH;
    const ushort_t* Kh = Qh + DM;
    const ushort_t* Kl = Ql + DM;
    float* Cb = attn + (size_t)bh * TT * TT;

    extern __shared__ char smraw[];
    uint32_t smb = smem_u32(smraw);

    int tid = threadIdx.x;
    int wid = tid >> 5, L = tid & 31;
    int warp_row = (wid & 3) * 32;
    int warp_col = (wid >> 2) * 64;
    int ldrow = ((L >> 3) & 1) * 8 + (L & 7);
    int ldk   = L >> 4;

    int lrow = tid >> 1;
    int lc0  = (tid & 1) * 4;

#pragma unroll
    for (int j = 0; j < 4; j++) {
        int c = lc0 + j;
        uint32_t d = (uint32_t)(lrow * 128 + ((c ^ (lrow & 7)) * 16));
        cp16(smb + QH + d, Qh + (size_t)(row0 + lrow) * ldq + c * 8);
        cp16(smb + QL + d, Ql + (size_t)(row0 + lrow) * ldq + c * 8);
        cp16(smb + KST + d, Kh + (size_t)lrow * ldq + c * 8);
        cp16(smb + KST + KLOFF + d, Kl + (size_t)lrow * ldq + c * 8);
    }
    CP_COMMIT();

    for (int jt = 0; jt <= by; jt++) {
        if (jt + 1 <= by) {
            uint32_t sb = smb + KST + ((jt + 1) & 1) * KSTG;
#pragma unroll
            for (int j = 0; j < 4; j++) {
                int c = lc0 + j;
                uint32_t d = (uint32_t)(lrow * 128 + ((c ^ (lrow & 7)) * 16));
                cp16(sb + d, Kh + (size_t)((jt + 1) * 128 + lrow) * ldq + c * 8);
                cp16(sb + KLOFF + d, Kl + (size_t)((jt + 1) * 128 + lrow) * ldq + c * 8);
            }
        }
        CP_COMMIT();
        CP_WAIT1();
        __syncthreads();

        float acc[2][8][4];
#pragma unroll
        for (int i = 0; i < 2; i++)
#pragma unroll
            for (int j = 0; j < 8; j++)
#pragma unroll
                for (int q = 0; q < 4; q++) acc[i][j][q] = 0.f;

        uint32_t kb = smb + KST + (jt & 1) * KSTG;
#pragma unroll
        for (int s = 0; s < 4; s++) {
            int cbase = 2 * s + ldk;
            uint32_t ah[2][4], al[2][4];
#pragma unroll
            for (int mt = 0; mt < 2; mt++) {
                int rr = warp_row + mt * 16 + ldrow;
                uint32_t ra = (uint32_t)(rr * 128 + ((cbase ^ (rr & 7)) * 16));
                ldsm4(ah[mt], smb + QH + ra);
                ldsm4(al[mt], smb + QL + ra);
            }
#pragma unroll
            for (int np = 0; np < 4; np++) {
                int rr = warp_col + np * 16 + ldrow;
                uint32_t rb = (uint32_t)(rr * 128 + ((cbase ^ (rr & 7)) * 16));
                uint32_t bh4[4], bl4[4];
                ldsm4(bh4, kb + rb);
                ldsm4(bl4, kb + KLOFF + rb);
#pragma unroll
                for (int mt = 0; mt < 2; mt++) {
                    mma16816(acc[mt][2 * np],     ah[mt], bh4[0], bh4[2]);
                    mma16816(acc[mt][2 * np + 1], ah[mt], bh4[1], bh4[3]);
                }
#pragma unroll
                for (int mt = 0; mt < 2; mt++) {
                    mma16816(acc[mt][2 * np],     ah[mt], bl4[0], bl4[2]);
                    mma16816(acc[mt][2 * np + 1], ah[mt], bl4[1], bl4[3]);
                }
#pragma unroll
                for (int mt = 0; mt < 2; mt++) {
                    mma16816(acc[mt][2 * np],     al[mt], bh4[0], bh4[2]);
                    mma16816(acc[mt][2 * np + 1], al[mt], bh4[1], bh4[3]);
                }
            }
        }

        int col0 = jt * 128;
#pragma unroll
        for (int mt = 0; mt < 2; mt++) {
            int r0g = row0 + warp_row + mt * 16 + (L >> 2);
#pragma unroll
            for (int nt = 0; nt < 8; nt++) {
                int cg = col0 + warp_col + nt * 8 + (L & 3) * 2;
                float* p0 = Cb + (size_t)r0g * TT + cg;
                float* p1 = Cb + (size_t)(r0g + 8) * TT + cg;
                *(float2*)p0 = make_float2(0.125f * acc[mt][nt][0], 0.125f * acc[mt][nt][1]);
                *(float2*)p1 = make_float2(0.125f * acc[mt][nt][2], 0.125f * acc[mt][nt][3]);
            }
        }
        __syncthreads();
    }
}

// ---------------------------------------------------------------------------
__global__ __launch_bounds__(256) void softmax_split(float* __restrict__ attn,
                                                     ushort_t* __restrict__ ph,
                                                     ushort_t* __restrict__ pl) {
    __shared__ float red[256];
    size_t r = blockIdx.x;
    int q = (int)(r & (TT - 1));
    int len = q + 1;
    int keff = ((q >> 7) << 7) + 128;
    float* row = attn + r * (size_t)TT;
    int tid = threadIdx.x;
    int base = tid * 8;
    bool act = base < keff;

    float vals[8];
    if (act) {
        float4 v0 = *(const float4*)(row + base);
        float4 v1 = *(const float4*)(row + base + 4);
        vals[0] = v0.x; vals[1] = v0.y; vals[2] = v0.z; vals[3] = v0.w;
        vals[4] = v1.x; vals[5] = v1.y; vals[6] = v1.z; vals[7] = v1.w;
    }

    float m = -INFINITY;
    if (act) {
#pragma unroll
        for (int j = 0; j < 8; j++) if (base + j < len) m = fmaxf(m, vals[j]);
    }
    red[tid] = m; __syncthreads();
#pragma unroll
    for (int s = 128; s > 0; s >>= 1) {
        if (tid < s) red[tid] = fmaxf(red[tid], red[tid + s]);
        __syncthreads();
    }
    m = red[0]; __syncthreads();

    float e[8]; float sum = 0.f;
#pragma unroll
    for (int j = 0; j < 8; j++) {
        e[j] = (act && base + j < len) ? __expf(vals[j] - m) : 0.f;
        sum += e[j];
    }
    red[tid] = sum; __syncthreads();
#pragma unroll
    for (int s = 128; s > 0; s >>= 1) {
        if (tid < s) red[tid] += red[tid + s];
        __syncthreads();
    }
    float inv = 1.0f / red[0];
#pragma unroll
    for (int j = 0; j < 8; j++) e[j] *= inv;

    *(float4*)(row + base) = make_float4(e[0], e[1], e[2], e[3]);
    *(float4*)(row + base + 4) = make_float4(e[4], e[5], e[6], e[7]);

    if (act) {
        ushort4 hh, ll;
        split2(e[0], hh.x, ll.x); split2(e[1], hh.y, ll.y);
        split2(e[2], hh.z, ll.z); split2(e[3], hh.w, ll.w);
        *(ushort4*)(ph + r * (size_t)TT + base) = hh;
        *(ushort4*)(pl + r * (size_t)TT + base) = ll;
        split2(e[4], hh.x, ll.x); split2(e[5], hh.y, ll.y);
        split2(e[6], hh.z, ll.z); split2(e[7], hh.w, ll.w);
        *(ushort4*)(ph + r * (size_t)TT + base + 4) = hh;
        *(ushort4*)(pl + r * (size_t)TT + base + 4) = ll;
    }
}

// ---------------------------------------------------------------------------
extern "C" void kernel_launch(void* const* d_in, const int* in_sizes, int n_in,
                              void* d_out, int out_size)
{
    const float* x      = (const float*)d_in[0];
    const float* w_qkv  = (const float*)d_in[1];
    const float* w_proj = (const float*)d_in[2];
    float* out = (float*)d_out;

    ushort_t *xh, *xl, *wqkvh, *wqkvl, *wprojh, *wprojl, *qkvh, *qkvl;
    ushort_t *vth, *vtl, *ph, *pl, *ctxh, *ctxl;
    float *qkv, *ctx, *attn_fb;
    cudaGetSymbolAddress((void**)&xh, g_xh);
    cudaGetSymbolAddress((void**)&xl, g_xl);
    cudaGetSymbolAddress((void**)&wqkvh, g_wqkvh);
    cudaGetSymbolAddress((void**)&wqkvl, g_wqkvl);
    cudaGetSymbolAddress((void**)&wprojh, g_wprojh);
    cudaGetSymbolAddress((void**)&wprojl, g_wprojl);
    cudaGetSymbolAddress((void**)&qkv, g_qkv);
    cudaGetSymbolAddress((void**)&qkvh, g_qkvh);
    cudaGetSymbolAddress((void**)&qkvl, g_qkvl);
    cudaGetSymbolAddress((void**)&vth, g_vth);
    cudaGetSymbolAddress((void**)&vtl, g_vtl);
    cudaGetSymbolAddress((void**)&ph, g_ph);
    cudaGetSymbolAddress((void**)&pl, g_pl);
    cudaGetSymbolAddress((void**)&ctx, g_ctx);
    cudaGetSymbolAddress((void**)&ctxh, g_ctxh);
    cudaGetSymbolAddress((void**)&ctxl, g_ctxl);
    cudaGetSymbolAddress((void**)&attn_fb, g_attn_fallback);

    const size_t out_elems = (size_t)BB * TT * DM;
    float* attn = ((size_t)out_size > out_elems) ? (out + out_elems) : attn_fb;

    const int SMEM128 = 3 * (2 * 128 * 64 + 2 * 128 * 64);
    const int SMEM64  = 3 * (2 * 128 * 64 + 2 * 64 * 64);
    const int SMEMSC  = 32768 + 2 * 32768;
    cudaFuncSetAttribute(gemm_mma2<128, 0>, cudaFuncAttributeMaxDynamicSharedMemorySize, SMEM128);
    cudaFuncSetAttribute(gemm_mma2<64, 2>,  cudaFuncAttributeMaxDynamicSharedMemorySize, SMEM64);
    cudaFuncSetAttribute(scores_mma, cudaFuncAttributeMaxDynamicSharedMemorySize, SMEMSC);

    const int M = BB * TT;

    split_arr<<<M * DM / 4 / 256, 256>>>((const float4*)x, (ushort4*)xh, (ushort4*)xl, M * DM / 4);
    split_arr<<<3 * DM * DM / 4 / 256, 256>>>((const float4*)w_qkv, (ushort4*)wqkvh, (ushort4*)wqkvl, 3 * DM * DM / 4);
    split_arr<<<DM * DM / 4 / 256, 256>>>((const float4*)w_proj, (ushort4*)wprojh, (ushort4*)wprojl, DM * DM / 4);

    gemm_mma2<128, 0><<<dim3(3 * DM / 128, M / 128, 1), 256, SMEM128>>>(
        xh, xl, wqkvh, wqkvl, qkv, DM, DM, DM, 3 * DM,
        0, 0, 0, 0, 0, 0, 1.0f);

    split_arr<<<M * 3 * DM / 4 / 256, 256>>>((const float4*)qkv, (ushort4*)qkvh, (ushort4*)qkvl, M * 3 * DM / 4);
    transpose_v<<<dim3(DH / 32, TT / 32, BB * NH), dim3(32, 8)>>>(qkv, vth, vtl);

    scores_mma<<<dim3(16, 1, BB * NH), 256, SMEMSC>>>(qkvh, qkvl, attn);

    softmax_split<<<BB * NH * TT, 256>>>(attn, ph, pl);

    gemm_mma2<64, 2><<<dim3(1, TT / 128, BB * NH), 256, SMEM64>>>(
        ph, pl, vth, vtl, ctx, TT, TT, TT, DM,
        (long long)NH * TT * TT, (long long)TT * TT,
        (long long)NH * DH * TT, (long long)DH * TT,
        (long long)TT * DM, DH, 1.0f);

    split_arr<<<M * DM / 4 / 256, 256>>>((const float4*)ctx, (ushort4*)ctxh, (ushort4*)ctxl, M * DM / 4);
    gemm_mma2<128, 0><<<dim3(DM / 128, M / 128, 1), 256, SMEM128>>>(
        ctxh, ctxl, wprojh, wprojl, out, DM, DM, DM, DM,
        0, 0, 0, 0, 0, 0, 1.0f);
}

// round 6
// speedup vs baseline: 3.1810x; 1.7886x over previous
#include <cuda_runtime.h>
#include <cuda_fp16.h>
#include <cstdint>
#include <math.h>

#define NH 16
#define DM 1024
#define DH 64
#define BB 2
#define TT 2048

typedef unsigned short ushort_t;

// ---------------------------------------------------------------------------
// Scratch (__device__ globals). All tensor operands as single fp16.
// ---------------------------------------------------------------------------
__device__ ushort_t g_xf[(size_t)BB * TT * DM];
__device__ ushort_t g_wqkvf[(size_t)3 * DM * DM];
__device__ ushort_t g_wprojf[(size_t)DM * DM];
__device__ float    g_qkv[(size_t)BB * TT * 3 * DM];
__device__ ushort_t g_qkvf[(size_t)BB * TT * 3 * DM];
__device__ ushort_t g_vtf[(size_t)BB * NH * DH * TT];   // V^T per head [64][2048]
__device__ ushort_t g_pf[(size_t)BB * NH * TT * TT];    // fp16 attn probs
__device__ float    g_ctx[(size_t)BB * TT * DM];
__device__ ushort_t g_ctxf[(size_t)BB * TT * DM];
__device__ float    g_attn_fallback[(size_t)BB * NH * TT * TT];

// ---------------------------------------------------------------------------
__device__ __forceinline__ uint32_t smem_u32(const void* p) {
    uint32_t a;
    asm("{ .reg .u64 t; cvta.to.shared.u64 t, %1; cvt.u32.u64 %0, t; }" : "=r"(a) : "l"(p));
    return a;
}
__device__ __forceinline__ void cp16(uint32_t dst, const void* src) {
    unsigned long long g = (unsigned long long)__cvta_generic_to_global(src);
    asm volatile("cp.async.cg.shared.global [%0], [%1], 16;" :: "r"(dst), "l"(g));
}
#define CP_COMMIT() asm volatile("cp.async.commit_group;" ::: "memory")
#define CP_WAIT1()  asm volatile("cp.async.wait_group 1;" ::: "memory")
#define CP_WAIT2()  asm volatile("cp.async.wait_group 2;" ::: "memory")

__device__ __forceinline__ void ldsm4(uint32_t* r, uint32_t addr) {
    asm volatile("ldmatrix.sync.aligned.m8n8.x4.shared.b16 {%0,%1,%2,%3}, [%4];"
        : "=r"(r[0]), "=r"(r[1]), "=r"(r[2]), "=r"(r[3]) : "r"(addr));
}
__device__ __forceinline__ void mma16816(float* c, const uint32_t* a, uint32_t b0, uint32_t b1) {
    asm volatile("mma.sync.aligned.m16n8k16.row.col.f32.f16.f16.f32 "
        "{%0,%1,%2,%3}, {%4,%5,%6,%7}, {%8,%9}, {%0,%1,%2,%3};"
        : "+f"(c[0]), "+f"(c[1]), "+f"(c[2]), "+f"(c[3])
        : "r"(a[0]), "r"(a[1]), "r"(a[2]), "r"(a[3]), "r"(b0), "r"(b1));
}
__device__ __forceinline__ ushort_t f2h(float x) {
    return __half_as_ushort(__float2half_rn(x));
}

// ---------------------------------------------------------------------------
__global__ __launch_bounds__(256) void conv_arr(const float4* __restrict__ in,
                                                ushort4* __restrict__ o, int n4) {
    int i = blockIdx.x * 256 + threadIdx.x;
    if (i < n4) {
        float4 v = in[i];
        o[i] = make_ushort4(f2h(v.x), f2h(v.y), f2h(v.z), f2h(v.w));
    }
}

__global__ __launch_bounds__(256) void transpose_v(const float* __restrict__ qkv,
                                                   ushort_t* __restrict__ vtf) {
    __shared__ ushort_t tile[32][33];
    int bh = blockIdx.z;
    int b = bh >> 4, h = bh & 15;
    int t0 = blockIdx.y * 32, d0 = blockIdx.x * 32;
    int tx = threadIdx.x, ty = threadIdx.y;
#pragma unroll
    for (int j = 0; j < 4; j++) {
        int t = t0 + ty + j * 8;
        int d = d0 + tx;
        tile[ty + j * 8][tx] = f2h(qkv[((size_t)b * TT + t) * (3 * DM) + 2 * DM + h * DH + d]);
    }
    __syncthreads();
#pragma unroll
    for (int j = 0; j < 4; j++) {
        int d = d0 + ty + j * 8;
        int t = t0 + tx;
        vtf[((size_t)bh * DH + d) * TT + t] = tile[tx][ty + j * 8];
    }
}

// ---------------------------------------------------------------------------
// fp16 mma.sync GEMM: C[M,N] = alpha * A[M,K] * B[N,K]^T. KC=32, 3-stage
// cp.async, XOR-swizzled smem (rows 64B). BM=128, BN in {64,128}. 8 warps.
// CMODE: 0 none, 2 causal K clamp.
// ---------------------------------------------------------------------------
template <int BN, int CMODE>
__global__ __launch_bounds__(256, 2) void gemm_mma3(
    const ushort_t* __restrict__ Ap, const ushort_t* __restrict__ Bp,
    float* __restrict__ C,
    int K, int lda, int ldb, int ldc,
    long long sAb, long long sAh, long long sBb, long long sBh,
    long long sCb, long long sCh, float alpha)
{
    constexpr int NP = BN / 32;
    constexpr int A_BYTES = 128 * 64;
    constexpr int B_BYTES = BN * 64;
    constexpr int STAGE = A_BYTES + B_BYTES;
    constexpr int OFF_B = A_BYTES;
    constexpr int NBJ = (BN * 4) / 256;        // B cp16 per thread (2 or 1)

    int bx = blockIdx.x, by = blockIdx.y, bz = blockIdx.z;
    int row0 = by * 128, col0 = bx * BN;

    int b = bz >> 4, h = bz & 15;
    Ap += (size_t)b * sAb + (size_t)h * sAh;
    Bp += (size_t)b * sBb + (size_t)h * sBh;
    C  += (size_t)b * sCb + (size_t)h * sCh;

    extern __shared__ char smraw[];
    uint32_t smb = smem_u32(smraw);

    int tid = threadIdx.x;
    int wid = tid >> 5, L = tid & 31;
    int warp_row = (wid & 3) * 32;
    int warp_col = (wid >> 2) * (BN / 2);

    int Keff = (CMODE == 2) ? min(K, row0 + 128) : K;
    int nc = Keff >> 5;

    int ldrow = ((L >> 3) & 1) * 8 + (L & 7);
    int ldk   = L >> 4;

    float acc[2][2 * NP][4];
#pragma unroll
    for (int i = 0; i < 2; i++)
#pragma unroll
        for (int j = 0; j < 2 * NP; j++)
#pragma unroll
            for (int q = 0; q < 4; q++) acc[i][j][q] = 0.f;

    auto load_stage = [&](uint32_t sb, int k0) {
#pragma unroll
        for (int j = 0; j < 2; j++) {
            int slot = tid * 2 + j;
            int r = slot >> 2, c = slot & 3;
            uint32_t d = (uint32_t)(r * 64 + ((c ^ ((r >> 1) & 3)) * 16));
            cp16(sb + d, Ap + (size_t)(row0 + r) * lda + k0 + c * 8);
        }
#pragma unroll
        for (int j = 0; j < NBJ; j++) {
            int slot = tid * NBJ + j;
            int r = slot >> 2, c = slot & 3;
            uint32_t d = (uint32_t)(r * 64 + ((c ^ ((r >> 1) & 3)) * 16));
            cp16(sb + OFF_B + d, Bp + (size_t)(col0 + r) * ldb + k0 + c * 8);
        }
    };

#pragma unroll
    for (int s = 0; s < 2; s++) {
        if (s < nc) load_stage(smb + s * STAGE, s * 32);
        CP_COMMIT();
    }

    for (int ch = 0; ch < nc; ch++) {
        int sN = ch + 2;
        if (sN < nc) load_stage(smb + (sN % 3) * STAGE, sN * 32);
        CP_COMMIT();
        CP_WAIT2();
        __syncthreads();

        uint32_t sb = smb + (ch % 3) * STAGE;
#pragma unroll
        for (int s = 0; s < 2; s++) {
            int cbase = 2 * s + ldk;
            uint32_t af[2][4];
#pragma unroll
            for (int mt = 0; mt < 2; mt++) {
                int rr = warp_row + mt * 16 + ldrow;
                uint32_t ra = (uint32_t)(rr * 64 + ((cbase ^ ((rr >> 1) & 3)) * 16));
                ldsm4(af[mt], sb + ra);
            }
#pragma unroll
            for (int np = 0; np < NP; np++) {
                int rr = warp_col + np * 16 + ldrow;
                uint32_t rb = (uint32_t)(rr * 64 + ((cbase ^ ((rr >> 1) & 3)) * 16));
                uint32_t bf[4];
                ldsm4(bf, sb + OFF_B + rb);
#pragma unroll
                for (int mt = 0; mt < 2; mt++) {
                    mma16816(acc[mt][2 * np],     af[mt], bf[0], bf[2]);
                    mma16816(acc[mt][2 * np + 1], af[mt], bf[1], bf[3]);
                }
            }
        }
        __syncthreads();
    }

#pragma unroll
    for (int mt = 0; mt < 2; mt++) {
        int r0g = row0 + warp_row + mt * 16 + (L >> 2);
#pragma unroll
        for (int nt = 0; nt < 2 * NP; nt++) {
            int cg = col0 + warp_col + nt * 8 + (L & 3) * 2;
            float* p0 = C + (size_t)r0g * ldc + cg;
            float* p1 = C + (size_t)(r0g + 8) * ldc + cg;
            *(float2*)p0 = make_float2(alpha * acc[mt][nt][0], alpha * acc[mt][nt][1]);
            *(float2*)p1 = make_float2(alpha * acc[mt][nt][2], alpha * acc[mt][nt][3]);
        }
    }
}

// ---------------------------------------------------------------------------
// Scores: persistent Q tile (128x64 fp16), causal K-row sweep, depth-1 prefetch.
// Rows 128B; swz c' = c ^ (r&7). grid (16, 1, BB*NH), by = 15 - bx.
// ---------------------------------------------------------------------------
__global__ __launch_bounds__(256, 2) void scores_mma(
    const ushort_t* __restrict__ qkvf, float* __restrict__ attn)
{
    constexpr int QOF = 0;
    constexpr int KST = 16384;
    constexpr int KSTG = 16384;
    const int ldq = 3 * DM;

    int by = 15 - blockIdx.x;
    int bh = blockIdx.z;
    int b = bh >> 4, h = bh & 15;
    int row0 = by * 128;

    const ushort_t* Q = qkvf + (size_t)b * TT * 3 * DM + h * DH;
    const ushort_t* Kp = Q + DM;
    float* Cb = attn + (size_t)bh * TT * TT;

    extern __shared__ char smraw[];
    uint32_t smb = smem_u32(smraw);

    int tid = threadIdx.x;
    int wid = tid >> 5, L = tid & 31;
    int warp_row = (wid & 3) * 32;
    int warp_col = (wid >> 2) * 64;
    int ldrow = ((L >> 3) & 1) * 8 + (L & 7);
    int ldk   = L >> 4;

    int lrow = tid >> 1;
    int lc0  = (tid & 1) * 4;

    // Q rows are 64 fp16 = 128B = 8 chunks; each thread loads 4 of one row.
    // (two threads per row cover chunks 0-3 / 4-7 via lc0)
#pragma unroll
    for (int j = 0; j < 4; j++) {
        int c = lc0 + j;
        uint32_t d = (uint32_t)(lrow * 128 + ((c ^ (lrow & 7)) * 16));
        cp16(smb + QOF + d, Q + (size_t)(row0 + lrow) * ldq + c * 8);
        cp16(smb + KST + d, Kp + (size_t)lrow * ldq + c * 8);
    }
    CP_COMMIT();

    for (int jt = 0; jt <= by; jt++) {
        if (jt + 1 <= by) {
            uint32_t sb = smb + KST + ((jt + 1) & 1) * KSTG;
#pragma unroll
            for (int j = 0; j < 4; j++) {
                int c = lc0 + j;
                uint32_t d = (uint32_t)(lrow * 128 + ((c ^ (lrow & 7)) * 16));
                cp16(sb + d, Kp + (size_t)((jt + 1) * 128 + lrow) * ldq + c * 8);
            }
        }
        CP_COMMIT();
        CP_WAIT1();
        __syncthreads();

        float acc[2][8][4];
#pragma unroll
        for (int i = 0; i < 2; i++)
#pragma unroll
            for (int j = 0; j < 8; j++)
#pragma unroll
                for (int q = 0; q < 4; q++) acc[i][j][q] = 0.f;

        uint32_t kb = smb + KST + (jt & 1) * KSTG;
#pragma unroll
        for (int s = 0; s < 4; s++) {
            int cbase = 2 * s + ldk;
            uint32_t af[2][4];
#pragma unroll
            for (int mt = 0; mt < 2; mt++) {
                int rr = warp_row + mt * 16 + ldrow;
                uint32_t ra = (uint32_t)(rr * 128 + ((cbase ^ (rr & 7)) * 16));
                ldsm4(af[mt], smb + QOF + ra);
            }
#pragma unroll
            for (int np = 0; np < 4; np++) {
                int rr = warp_col + np * 16 + ldrow;
                uint32_t rb = (uint32_t)(rr * 128 + ((cbase ^ (rr & 7)) * 16));
                uint32_t bf[4];
                ldsm4(bf, kb + rb);
#pragma unroll
                for (int mt = 0; mt < 2; mt++) {
                    mma16816(acc[mt][2 * np],     af[mt], bf[0], bf[2]);
                    mma16816(acc[mt][2 * np + 1], af[mt], bf[1], bf[3]);
                }
            }
        }

        int col0 = jt * 128;
#pragma unroll
        for (int mt = 0; mt < 2; mt++) {
            int r0g = row0 + warp_row + mt * 16 + (L >> 2);
#pragma unroll
            for (int nt = 0; nt < 8; nt++) {
                int cg = col0 + warp_col + nt * 8 + (L & 3) * 2;
                float* p0 = Cb + (size_t)r0g * TT + cg;
                float* p1 = Cb + (size_t)(r0g + 8) * TT + cg;
                *(float2*)p0 = make_float2(0.125f * acc[mt][nt][0], 0.125f * acc[mt][nt][1]);
                *(float2*)p1 = make_float2(0.125f * acc[mt][nt][2], 0.125f * acc[mt][nt][3]);
            }
        }
        __syncthreads();
    }
}

// ---------------------------------------------------------------------------
// Causal softmax: reads valid (128-rounded) prefix; writes fp32 row with exact
// zeros in tail + fp16 probs for the valid prefix.
// ---------------------------------------------------------------------------
__global__ __launch_bounds__(256) void softmax_h(float* __restrict__ attn,
                                                 ushort_t* __restrict__ pf) {
    __shared__ float red[256];
    size_t r = blockIdx.x;
    int q = (int)(r & (TT - 1));
    int len = q + 1;
    int keff = ((q >> 7) << 7) + 128;
    float* row = attn + r * (size_t)TT;
    int tid = threadIdx.x;
    int base = tid * 8;
    bool act = base < keff;

    float vals[8];
    if (act) {
        float4 v0 = *(const float4*)(row + base);
        float4 v1 = *(const float4*)(row + base + 4);
        vals[0] = v0.x; vals[1] = v0.y; vals[2] = v0.z; vals[3] = v0.w;
        vals[4] = v1.x; vals[5] = v1.y; vals[6] = v1.z; vals[7] = v1.w;
    }

    float m = -INFINITY;
    if (act) {
#pragma unroll
        for (int j = 0; j < 8; j++) if (base + j < len) m = fmaxf(m, vals[j]);
    }
    red[tid] = m; __syncthreads();
#pragma unroll
    for (int s = 128; s > 0; s >>= 1) {
        if (tid < s) red[tid] = fmaxf(red[tid], red[tid + s]);
        __syncthreads();
    }
    m = red[0]; __syncthreads();

    float e[8]; float sum = 0.f;
#pragma unroll
    for (int j = 0; j < 8; j++) {
        e[j] = (act && base + j < len) ? __expf(vals[j] - m) : 0.f;
        sum += e[j];
    }
    red[tid] = sum; __syncthreads();
#pragma unroll
    for (int s = 128; s > 0; s >>= 1) {
        if (tid < s) red[tid] += red[tid + s];
        __syncthreads();
    }
    float inv = 1.0f / red[0];
#pragma unroll
    for (int j = 0; j < 8; j++) e[j] *= inv;

    *(float4*)(row + base) = make_float4(e[0], e[1], e[2], e[3]);
    *(float4*)(row + base + 4) = make_float4(e[4], e[5], e[6], e[7]);

    if (act) {
        *(ushort4*)(pf + r * (size_t)TT + base) =
            make_ushort4(f2h(e[0]), f2h(e[1]), f2h(e[2]), f2h(e[3]));
        *(ushort4*)(pf + r * (size_t)TT + base + 4) =
            make_ushort4(f2h(e[4]), f2h(e[5]), f2h(e[6]), f2h(e[7]));
    }
}

// ---------------------------------------------------------------------------
extern "C" void kernel_launch(void* const* d_in, const int* in_sizes, int n_in,
                              void* d_out, int out_size)
{
    const float* x      = (const float*)d_in[0];
    const float* w_qkv  = (const float*)d_in[1];
    const float* w_proj = (const float*)d_in[2];
    float* out = (float*)d_out;

    ushort_t *xf, *wqkvf, *wprojf, *qkvf, *vtf, *pf, *ctxf;
    float *qkv, *ctx, *attn_fb;
    cudaGetSymbolAddress((void**)&xf, g_xf);
    cudaGetSymbolAddress((void**)&wqkvf, g_wqkvf);
    cudaGetSymbolAddress((void**)&wprojf, g_wprojf);
    cudaGetSymbolAddress((void**)&qkv, g_qkv);
    cudaGetSymbolAddress((void**)&qkvf, g_qkvf);
    cudaGetSymbolAddress((void**)&vtf, g_vtf);
    cudaGetSymbolAddress((void**)&pf, g_pf);
    cudaGetSymbolAddress((void**)&ctx, g_ctx);
    cudaGetSymbolAddress((void**)&ctxf, g_ctxf);
    cudaGetSymbolAddress((void**)&attn_fb, g_attn_fallback);

    const size_t out_elems = (size_t)BB * TT * DM;
    float* attn = ((size_t)out_size > out_elems) ? (out + out_elems) : attn_fb;

    const int SMEM128 = 3 * (128 * 64 + 128 * 64);   // 49152
    const int SMEM64  = 3 * (128 * 64 + 64 * 64);    // 36864
    const int SMEMSC  = 16384 + 2 * 16384;           // 49152
    cudaFuncSetAttribute(gemm_mma3<128, 0>, cudaFuncAttributeMaxDynamicSharedMemorySize, SMEM128);
    cudaFuncSetAttribute(gemm_mma3<64, 2>,  cudaFuncAttributeMaxDynamicSharedMemorySize, SMEM64);
    cudaFuncSetAttribute(scores_mma, cudaFuncAttributeMaxDynamicSharedMemorySize, SMEMSC);

    const int M = BB * TT;

    // 0) convert inputs to fp16
    conv_arr<<<M * DM / 4 / 256, 256>>>((const float4*)x, (ushort4*)xf, M * DM / 4);
    conv_arr<<<3 * DM * DM / 4 / 256, 256>>>((const float4*)w_qkv, (ushort4*)wqkvf, 3 * DM * DM / 4);
    conv_arr<<<DM * DM / 4 / 256, 256>>>((const float4*)w_proj, (ushort4*)wprojf, DM * DM / 4);

    // 1) qkv = x @ w_qkv^T
    gemm_mma3<128, 0><<<dim3(3 * DM / 128, M / 128, 1), 256, SMEM128>>>(
        xf, wqkvf, qkv, DM, DM, DM, 3 * DM, 0, 0, 0, 0, 0, 0, 1.0f);

    // 2) fp16 qkv + transpose V
    conv_arr<<<M * 3 * DM / 4 / 256, 256>>>((const float4*)qkv, (ushort4*)qkvf, M * 3 * DM / 4);
    transpose_v<<<dim3(DH / 32, TT / 32, BB * NH), dim3(32, 8)>>>(qkv, vtf);

    // 3) scores = q @ k^T * 1/8, causal
    scores_mma<<<dim3(16, 1, BB * NH), 256, SMEMSC>>>(qkvf, attn);

    // 4) causal softmax + fp16 probs
    softmax_h<<<BB * NH * TT, 256>>>(attn, pf);

    // 5) ctx = P @ V (V^T as NT operand), causal K clamp
    gemm_mma3<64, 2><<<dim3(1, TT / 128, BB * NH), 256, SMEM64>>>(
        pf, vtf, ctx, TT, TT, TT, DM,
        (long long)NH * TT * TT, (long long)TT * TT,
        (long long)NH * DH * TT, (long long)DH * TT,
        (long long)TT * DM, DH, 1.0f);

    // 6) fp16 ctx, out = ctx @ w_proj^T
    conv_arr<<<M * DM / 4 / 256, 256>>>((const float4*)ctx, (ushort4*)ctxf, M * DM / 4);
    gemm_mma3<128, 0><<<dim3(DM / 128, M / 128, 1), 256, SMEM128>>>(
        ctxf, wprojf, out, DM, DM, DM, DM, 0, 0, 0, 0, 0, 0, 1.0f);
}

// round 7
// speedup vs baseline: 3.7640x; 1.1833x over previous
#include <cuda_runtime.h>
#include <cuda_fp16.h>
#include <cstdint>
#include <math.h>

#define NH 16
#define DM 1024
#define DH 64
#define BB 2
#define TT 2048

typedef unsigned short ushort_t;

// ---------------------------------------------------------------------------
__device__ ushort_t g_xf[(size_t)BB * TT * DM];
__device__ ushort_t g_wqkvf[(size_t)3 * DM * DM];
__device__ ushort_t g_wprojf[(size_t)DM * DM];
__device__ float    g_qkv[(size_t)BB * TT * 3 * DM];
__device__ ushort_t g_qkvf[(size_t)BB * TT * 3 * DM];
__device__ ushort_t g_vtf[(size_t)BB * NH * DH * TT];   // V^T per head [64][2048]
__device__ ushort_t g_ctxf[(size_t)BB * TT * DM];
__device__ float    g_attn_fallback[(size_t)BB * NH * TT * TT];

// ---------------------------------------------------------------------------
__device__ __forceinline__ uint32_t smem_u32(const void* p) {
    uint32_t a;
    asm("{ .reg .u64 t; cvta.to.shared.u64 t, %1; cvt.u32.u64 %0, t; }" : "=r"(a) : "l"(p));
    return a;
}
__device__ __forceinline__ void cp16(uint32_t dst, const void* src) {
    unsigned long long g = (unsigned long long)__cvta_generic_to_global(src);
    asm volatile("cp.async.cg.shared.global [%0], [%1], 16;" :: "r"(dst), "l"(g));
}
#define CP_COMMIT() asm volatile("cp.async.commit_group;" ::: "memory")
#define CP_WAIT0()  asm volatile("cp.async.wait_group 0;" ::: "memory")
#define CP_WAIT1()  asm volatile("cp.async.wait_group 1;" ::: "memory")
#define CP_WAIT2()  asm volatile("cp.async.wait_group 2;" ::: "memory")

__device__ __forceinline__ void ldsm4(uint32_t* r, uint32_t addr) {
    asm volatile("ldmatrix.sync.aligned.m8n8.x4.shared.b16 {%0,%1,%2,%3}, [%4];"
        : "=r"(r[0]), "=r"(r[1]), "=r"(r[2]), "=r"(r[3]) : "r"(addr));
}
__device__ __forceinline__ void mma16816(float* c, const uint32_t* a, uint32_t b0, uint32_t b1) {
    asm volatile("mma.sync.aligned.m16n8k16.row.col.f32.f16.f16.f32 "
        "{%0,%1,%2,%3}, {%4,%5,%6,%7}, {%8,%9}, {%0,%1,%2,%3};"
        : "+f"(c[0]), "+f"(c[1]), "+f"(c[2]), "+f"(c[3])
        : "r"(a[0]), "r"(a[1]), "r"(a[2]), "r"(a[3]), "r"(b0), "r"(b1));
}
__device__ __forceinline__ ushort_t f2h(float x) {
    return __half_as_ushort(__float2half_rn(x));
}
__device__ __forceinline__ uint32_t f2h2(float a, float b) {
    __half2 h = __floats2half2_rn(a, b);
    return *(uint32_t*)&h;
}

// ---------------------------------------------------------------------------
__global__ __launch_bounds__(256) void conv_arr(const float4* __restrict__ in,
                                                ushort4* __restrict__ o, int n4) {
    int i = blockIdx.x * 256 + threadIdx.x;
    if (i < n4) {
        float4 v = in[i];
        o[i] = make_ushort4(f2h(v.x), f2h(v.y), f2h(v.z), f2h(v.w));
    }
}

__global__ __launch_bounds__(256) void transpose_v(const float* __restrict__ qkv,
                                                   ushort_t* __restrict__ vtf) {
    __shared__ ushort_t tile[32][33];
    int bh = blockIdx.z;
    int b = bh >> 4, h = bh & 15;
    int t0 = blockIdx.y * 32, d0 = blockIdx.x * 32;
    int tx = threadIdx.x, ty = threadIdx.y;
#pragma unroll
    for (int j = 0; j < 4; j++) {
        int t = t0 + ty + j * 8;
        int d = d0 + tx;
        tile[ty + j * 8][tx] = f2h(qkv[((size_t)b * TT + t) * (3 * DM) + 2 * DM + h * DH + d]);
    }
    __syncthreads();
#pragma unroll
    for (int j = 0; j < 4; j++) {
        int d = d0 + ty + j * 8;
        int t = t0 + tx;
        vtf[((size_t)bh * DH + d) * TT + t] = tile[tx][ty + j * 8];
    }
}

// ---------------------------------------------------------------------------
// fp16 mma.sync GEMM (dense): C[M,N] = alpha * A[M,K] * B[N,K]^T. KC=32,
// 3-stage cp.async, XOR-swizzled smem. BM=128, BN=128. 8 warps.
// ---------------------------------------------------------------------------
template <int BN>
__global__ __launch_bounds__(256, 2) void gemm_mma3(
    const ushort_t* __restrict__ Ap, const ushort_t* __restrict__ Bp,
    float* __restrict__ C, int K, int lda, int ldb, int ldc, float alpha)
{
    constexpr int NP = BN / 32;
    constexpr int A_BYTES = 128 * 64;
    constexpr int B_BYTES = BN * 64;
    constexpr int STAGE = A_BYTES + B_BYTES;
    constexpr int OFF_B = A_BYTES;
    constexpr int NBJ = (BN * 4) / 256;

    int bx = blockIdx.x, by = blockIdx.y;
    int row0 = by * 128, col0 = bx * BN;

    extern __shared__ char smraw[];
    uint32_t smb = smem_u32(smraw);

    int tid = threadIdx.x;
    int wid = tid >> 5, L = tid & 31;
    int warp_row = (wid & 3) * 32;
    int warp_col = (wid >> 2) * (BN / 2);

    int nc = K >> 5;
    int ldrow = ((L >> 3) & 1) * 8 + (L & 7);
    int ldk   = L >> 4;

    float acc[2][2 * NP][4];
#pragma unroll
    for (int i = 0; i < 2; i++)
#pragma unroll
        for (int j = 0; j < 2 * NP; j++)
#pragma unroll
            for (int q = 0; q < 4; q++) acc[i][j][q] = 0.f;

    auto load_stage = [&](uint32_t sb, int k0) {
#pragma unroll
        for (int j = 0; j < 2; j++) {
            int slot = tid * 2 + j;
            int r = slot >> 2, c = slot & 3;
            uint32_t d = (uint32_t)(r * 64 + ((c ^ ((r >> 1) & 3)) * 16));
            cp16(sb + d, Ap + (size_t)(row0 + r) * lda + k0 + c * 8);
        }
#pragma unroll
        for (int j = 0; j < NBJ; j++) {
            int slot = tid * NBJ + j;
            int r = slot >> 2, c = slot & 3;
            uint32_t d = (uint32_t)(r * 64 + ((c ^ ((r >> 1) & 3)) * 16));
            cp16(sb + OFF_B + d, Bp + (size_t)(col0 + r) * ldb + k0 + c * 8);
        }
    };

#pragma unroll
    for (int s = 0; s < 2; s++) {
        if (s < nc) load_stage(smb + s * STAGE, s * 32);
        CP_COMMIT();
    }

    for (int ch = 0; ch < nc; ch++) {
        int sN = ch + 2;
        if (sN < nc) load_stage(smb + (sN % 3) * STAGE, sN * 32);
        CP_COMMIT();
        CP_WAIT2();
        __syncthreads();

        uint32_t sb = smb + (ch % 3) * STAGE;
#pragma unroll
        for (int s = 0; s < 2; s++) {
            int cbase = 2 * s + ldk;
            uint32_t af[2][4];
#pragma unroll
            for (int mt = 0; mt < 2; mt++) {
                int rr = warp_row + mt * 16 + ldrow;
                uint32_t ra = (uint32_t)(rr * 64 + ((cbase ^ ((rr >> 1) & 3)) * 16));
                ldsm4(af[mt], sb + ra);
            }
#pragma unroll
            for (int np = 0; np < NP; np++) {
                int rr = warp_col + np * 16 + ldrow;
                uint32_t rb = (uint32_t)(rr * 64 + ((cbase ^ ((rr >> 1) & 3)) * 16));
                uint32_t bf[4];
                ldsm4(bf, sb + OFF_B + rb);
#pragma unroll
                for (int mt = 0; mt < 2; mt++) {
                    mma16816(acc[mt][2 * np],     af[mt], bf[0], bf[2]);
                    mma16816(acc[mt][2 * np + 1], af[mt], bf[1], bf[3]);
                }
            }
        }
        __syncthreads();
    }

#pragma unroll
    for (int mt = 0; mt < 2; mt++) {
        int r0g = row0 + warp_row + mt * 16 + (L >> 2);
#pragma unroll
        for (int nt = 0; nt < 2 * NP; nt++) {
            int cg = col0 + warp_col + nt * 8 + (L & 3) * 2;
            float* p0 = C + (size_t)r0g * ldc + cg;
            float* p1 = C + (size_t)(r0g + 8) * ldc + cg;
            *(float2*)p0 = make_float2(alpha * acc[mt][nt][0], alpha * acc[mt][nt][1]);
            *(float2*)p1 = make_float2(alpha * acc[mt][nt][2], alpha * acc[mt][nt][3]);
        }
    }
}

// ---------------------------------------------------------------------------
// Fused two-pass flash attention per (bh, 128-row Q tile):
// Pass A: sweep K tiles, compute S fragments, online (m, sum) row stats.
// Pass B: re-sweep, P = exp(S-m)/sum -> write attn fp32, pack P to A-frags,
// MMA against V^T tiles to accumulate O; write ctxf fp16. Zero-fills the
// causal tail of attn. grid (16, 1, BB*NH); by = 15 - bx.
// ---------------------------------------------------------------------------
__global__ __launch_bounds__(256) void attn_fused(
    const ushort_t* __restrict__ qkvf, const ushort_t* __restrict__ vtf,
    float* __restrict__ attn, ushort_t* __restrict__ ctxf)
{
    constexpr int QOF = 0;
    constexpr int KST = 16384;
    constexpr int KSTG = 16384;
    constexpr int VST = 49152;
    constexpr int VSTG = 16384;
    constexpr int RED = 81920;             // mbuf[2][128], sbuf[2][128]
    const int ldq = 3 * DM;

    int by = 15 - blockIdx.x;
    int bh = blockIdx.z;
    int b = bh >> 4, h = bh & 15;
    int row0 = by * 128;

    const ushort_t* Q  = qkvf + (size_t)b * TT * 3 * DM + h * DH;
    const ushort_t* Kp = Q + DM;
    const ushort_t* Vt = vtf + (size_t)bh * DH * TT;
    float* Cb = attn + (size_t)bh * TT * TT;

    extern __shared__ char smraw[];
    uint32_t smb = smem_u32(smraw);
    float* mbuf = (float*)(smraw + RED);
    float* sbuf = (float*)(smraw + RED + 1024);

    int tid = threadIdx.x;
    int wid = tid >> 5, L = tid & 31;
    int warp_row = (wid & 3) * 32;
    int wc = wid >> 2;
    int warp_col = wc * 64;
    int ldrow = ((L >> 3) & 1) * 8 + (L & 7);
    int ldk   = L >> 4;

    int lrow = tid >> 1;
    int lc0  = (tid & 1) * 4;
    int vrow = tid >> 2;
    int vc0  = (tid & 3) * 4;

    // ======================= PASS A: stats =======================
#pragma unroll
    for (int j = 0; j < 4; j++) {
        int c = lc0 + j;
        uint32_t d = (uint32_t)(lrow * 128 + ((c ^ (lrow & 7)) * 16));
        cp16(smb + QOF + d, Q + (size_t)(row0 + lrow) * ldq + c * 8);
        cp16(smb + KST + d, Kp + (size_t)lrow * ldq + c * 8);
    }
    CP_COMMIT();

    float mA[2][2], sA[2][2];
#pragma unroll
    for (int i = 0; i < 2; i++)
#pragma unroll
        for (int j = 0; j < 2; j++) { mA[i][j] = -1e30f; sA[i][j] = 0.f; }

    for (int jt = 0; jt <= by; jt++) {
        if (jt < by) {
            uint32_t sb = smb + KST + ((jt + 1) & 1) * KSTG;
#pragma unroll
            for (int j = 0; j < 4; j++) {
                int c = lc0 + j;
                uint32_t d = (uint32_t)(lrow * 128 + ((c ^ (lrow & 7)) * 16));
                cp16(sb + d, Kp + (size_t)((jt + 1) * 128 + lrow) * ldq + c * 8);
            }
        }
        CP_COMMIT();
        CP_WAIT1();
        __syncthreads();

        float acc[2][8][4];
#pragma unroll
        for (int i = 0; i < 2; i++)
#pragma unroll
            for (int j = 0; j < 8; j++)
#pragma unroll
                for (int q = 0; q < 4; q++) acc[i][j][q] = 0.f;

        uint32_t kb = smb + KST + (jt & 1) * KSTG;
#pragma unroll
        for (int s = 0; s < 4; s++) {
            int cbase = 2 * s + ldk;
            uint32_t af[2][4];
#pragma unroll
            for (int mt = 0; mt < 2; mt++) {
                int rr = warp_row + mt * 16 + ldrow;
                uint32_t ra = (uint32_t)(rr * 128 + ((cbase ^ (rr & 7)) * 16));
                ldsm4(af[mt], smb + QOF + ra);
            }
#pragma unroll
            for (int np = 0; np < 4; np++) {
                int rr = warp_col + np * 16 + ldrow;
                uint32_t rb = (uint32_t)(rr * 128 + ((cbase ^ (rr & 7)) * 16));
                uint32_t bf[4];
                ldsm4(bf, kb + rb);
#pragma unroll
                for (int mt = 0; mt < 2; mt++) {
                    mma16816(acc[mt][2 * np],     af[mt], bf[0], bf[2]);
                    mma16816(acc[mt][2 * np + 1], af[mt], bf[1], bf[3]);
                }
            }
        }

        int col0 = jt * 128;
        bool diag = (jt == by);
#pragma unroll
        for (int mt = 0; mt < 2; mt++) {
#pragma unroll
            for (int inst = 0; inst < 2; inst++) {
                int rg = row0 + warp_row + mt * 16 + inst * 8 + (L >> 2);
                float vv[16];
                float tm = -1e30f;
#pragma unroll
                for (int nt = 0; nt < 8; nt++) {
#pragma unroll
                    for (int e = 0; e < 2; e++) {
                        float v = acc[mt][nt][inst * 2 + e] * 0.125f;
                        if (diag) {
                            int kg = col0 + warp_col + nt * 8 + (L & 3) * 2 + e;
                            if (kg > rg) v = -1e30f;
                        }
                        vv[nt * 2 + e] = v;
                        tm = fmaxf(tm, v);
                    }
                }
                if (tm > -1e29f) {
                    float mo = mA[mt][inst];
                    float mn = fmaxf(mo, tm);
                    float ssum = 0.f;
#pragma unroll
                    for (int i = 0; i < 16; i++) ssum += __expf(vv[i] - mn);
                    sA[mt][inst] = sA[mt][inst] * __expf(mo - mn) + ssum;
                    mA[mt][inst] = mn;
                }
            }
        }
        __syncthreads();
    }

    // quad + cross-warp stat reduction
#pragma unroll
    for (int mt = 0; mt < 2; mt++) {
#pragma unroll
        for (int inst = 0; inst < 2; inst++) {
            float m = mA[mt][inst], s = sA[mt][inst];
#pragma unroll
            for (int off = 1; off <= 2; off <<= 1) {
                float mo = __shfl_xor_sync(0xffffffffu, m, off);
                float so = __shfl_xor_sync(0xffffffffu, s, off);
                float mn = fmaxf(m, mo);
                s = s * __expf(m - mn) + so * __expf(mo - mn);
                m = mn;
            }
            if ((L & 3) == 0) {
                int row = warp_row + mt * 16 + inst * 8 + (L >> 2);
                mbuf[wc * 128 + row] = m;
                sbuf[wc * 128 + row] = s;
            }
        }
    }
    __syncthreads();

    float mF[2][2], iS[2][2];
#pragma unroll
    for (int mt = 0; mt < 2; mt++) {
#pragma unroll
        for (int inst = 0; inst < 2; inst++) {
            int row = warp_row + mt * 16 + inst * 8 + (L >> 2);
            float m0 = mbuf[row], s0 = sbuf[row];
            float m1 = mbuf[128 + row], s1 = sbuf[128 + row];
            float mn = fmaxf(m0, m1);
            float s = s0 * __expf(m0 - mn) + s1 * __expf(m1 - mn);
            mF[mt][inst] = mn;
            iS[mt][inst] = 1.0f / s;
        }
    }
    CP_WAIT0();
    __syncthreads();

    // ======================= PASS B: P write + O accum =======================
#pragma unroll
    for (int j = 0; j < 4; j++) {
        int c = lc0 + j;
        uint32_t d = (uint32_t)(lrow * 128 + ((c ^ (lrow & 7)) * 16));
        cp16(smb + KST + d, Kp + (size_t)lrow * ldq + c * 8);
    }
#pragma unroll
    for (int j = 0; j < 4; j++) {
        int c2 = vc0 + j;
        uint32_t dv = (uint32_t)(vrow * 256 + ((c2 ^ (vrow & 7)) * 16));
        cp16(smb + VST + dv, Vt + (size_t)vrow * TT + c2 * 8);
    }
    CP_COMMIT();

    float O[2][8][4];
#pragma unroll
    for (int i = 0; i < 2; i++)
#pragma unroll
        for (int j = 0; j < 8; j++)
#pragma unroll
            for (int q = 0; q < 4; q++) O[i][j][q] = 0.f;

    for (int jt = 0; jt <= by; jt++) {
        if (jt < by) {
            uint32_t sb = smb + KST + ((jt + 1) & 1) * KSTG;
            uint32_t sv = smb + VST + ((jt + 1) & 1) * VSTG;
#pragma unroll
            for (int j = 0; j < 4; j++) {
                int c = lc0 + j;
                uint32_t d = (uint32_t)(lrow * 128 + ((c ^ (lrow & 7)) * 16));
                cp16(sb + d, Kp + (size_t)((jt + 1) * 128 + lrow) * ldq + c * 8);
            }
#pragma unroll
            for (int j = 0; j < 4; j++) {
                int c2 = vc0 + j;
                uint32_t dv = (uint32_t)(vrow * 256 + ((c2 ^ (vrow & 7)) * 16));
                cp16(sv + dv, Vt + (size_t)vrow * TT + (jt + 1) * 128 + c2 * 8);
            }
        }
        CP_COMMIT();
        CP_WAIT1();
        __syncthreads();

        float acc[2][8][4];
#pragma unroll
        for (int i = 0; i < 2; i++)
#pragma unroll
            for (int j = 0; j < 8; j++)
#pragma unroll
                for (int q = 0; q < 4; q++) acc[i][j][q] = 0.f;

        uint32_t kb = smb + KST + (jt & 1) * KSTG;
#pragma unroll
        for (int s = 0; s < 4; s++) {
            int cbase = 2 * s + ldk;
            uint32_t af[2][4];
#pragma unroll
            for (int mt = 0; mt < 2; mt++) {
                int rr = warp_row + mt * 16 + ldrow;
                uint32_t ra = (uint32_t)(rr * 128 + ((cbase ^ (rr & 7)) * 16));
                ldsm4(af[mt], smb + QOF + ra);
            }
#pragma unroll
            for (int np = 0; np < 4; np++) {
                int rr = warp_col + np * 16 + ldrow;
                uint32_t rb = (uint32_t)(rr * 128 + ((cbase ^ (rr & 7)) * 16));
                uint32_t bf[4];
                ldsm4(bf, kb + rb);
#pragma unroll
                for (int mt = 0; mt < 2; mt++) {
                    mma16816(acc[mt][2 * np],     af[mt], bf[0], bf[2]);
                    mma16816(acc[mt][2 * np + 1], af[mt], bf[1], bf[3]);
                }
            }
        }

        // P = exp(S - m) / sum (in place), mask diagonal
        int col0 = jt * 128;
        bool diag = (jt == by);
#pragma unroll
        for (int mt = 0; mt < 2; mt++) {
#pragma unroll
            for (int nt = 0; nt < 8; nt++) {
#pragma unroll
                for (int q = 0; q < 4; q++) {
                    int inst = q >> 1;
                    float v = acc[mt][nt][q] * 0.125f;
                    float p = __expf(v - mF[mt][inst]) * iS[mt][inst];
                    if (diag) {
                        int rg = row0 + warp_row + mt * 16 + inst * 8 + (L >> 2);
                        int kg = col0 + warp_col + nt * 8 + (L & 3) * 2 + (q & 1);
                        if (kg > rg) p = 0.f;
                    }
                    acc[mt][nt][q] = p;
                }
            }
        }

        // write normalized attn
#pragma unroll
        for (int mt = 0; mt < 2; mt++) {
            int r0g = row0 + warp_row + mt * 16 + (L >> 2);
#pragma unroll
            for (int nt = 0; nt < 8; nt++) {
                int cg = col0 + warp_col + nt * 8 + (L & 3) * 2;
                *(float2*)(Cb + (size_t)r0g * TT + cg) =
                    make_float2(acc[mt][nt][0], acc[mt][nt][1]);
                *(float2*)(Cb + (size_t)(r0g + 8) * TT + cg) =
                    make_float2(acc[mt][nt][2], acc[mt][nt][3]);
            }
        }

        // PV: P c-frags -> A-frags; V^T tile as B operand
        uint32_t kbv = smb + VST + (jt & 1) * VSTG;
#pragma unroll
        for (int g = 0; g < 4; g++) {
            uint32_t aa[2][4];
#pragma unroll
            for (int mt = 0; mt < 2; mt++) {
                aa[mt][0] = f2h2(acc[mt][2 * g][0],     acc[mt][2 * g][1]);
                aa[mt][1] = f2h2(acc[mt][2 * g][2],     acc[mt][2 * g][3]);
                aa[mt][2] = f2h2(acc[mt][2 * g + 1][0], acc[mt][2 * g + 1][1]);
                aa[mt][3] = f2h2(acc[mt][2 * g + 1][2], acc[mt][2 * g + 1][3]);
            }
            int cb = (warp_col >> 3) + 2 * g + ldk;
#pragma unroll
            for (int np2 = 0; np2 < 4; np2++) {
                int rr2 = np2 * 16 + ldrow;
                uint32_t rb = (uint32_t)(rr2 * 256 + ((cb ^ (rr2 & 7)) * 16));
                uint32_t bf[4];
                ldsm4(bf, kbv + rb);
#pragma unroll
                for (int mt = 0; mt < 2; mt++) {
                    mma16816(O[mt][2 * np2],     aa[mt], bf[0], bf[2]);
                    mma16816(O[mt][2 * np2 + 1], aa[mt], bf[1], bf[3]);
                }
            }
        }
        __syncthreads();
    }

    // zero-fill causal tail of attn
    int zt = 15 - by;
    if (zt > 0) {
        int r = tid >> 1;
        int halfc = zt * 64;
        float* base = Cb + (size_t)(row0 + r) * TT + (by + 1) * 128 + (tid & 1) * halfc;
        for (int i = 0; i < halfc; i += 4)
            *(float4*)(base + i) = make_float4(0.f, 0.f, 0.f, 0.f);
    }

    // O cross-warp reduce (reuse K stages as float[128][64]) + ctxf write
    float* Ob = (float*)(smraw + KST);
    if (wc == 1) {
#pragma unroll
        for (int mt = 0; mt < 2; mt++) {
            int row = warp_row + mt * 16 + (L >> 2);
#pragma unroll
            for (int nt = 0; nt < 8; nt++) {
                int col = nt * 8 + (L & 3) * 2;
                Ob[row * 64 + col]           = O[mt][nt][0];
                Ob[row * 64 + col + 1]       = O[mt][nt][1];
                Ob[(row + 8) * 64 + col]     = O[mt][nt][2];
                Ob[(row + 8) * 64 + col + 1] = O[mt][nt][3];
            }
        }
    }
    __syncthreads();
    if (wc == 0) {
#pragma unroll
        for (int mt = 0; mt < 2; mt++) {
            int row = warp_row + mt * 16 + (L >> 2);
#pragma unroll
            for (int nt = 0; nt < 8; nt++) {
                int col = nt * 8 + (L & 3) * 2;
                float v0 = O[mt][nt][0] + Ob[row * 64 + col];
                float v1 = O[mt][nt][1] + Ob[row * 64 + col + 1];
                float v2 = O[mt][nt][2] + Ob[(row + 8) * 64 + col];
                float v3 = O[mt][nt][3] + Ob[(row + 8) * 64 + col + 1];
                size_t a0 = ((size_t)b * TT + row0 + row) * DM + h * DH + col;
                size_t a1 = ((size_t)b * TT + row0 + row + 8) * DM + h * DH + col;
                *(uint32_t*)(ctxf + a0) = f2h2(v0, v1);
                *(uint32_t*)(ctxf + a1) = f2h2(v2, v3);
            }
        }
    }
}

// ---------------------------------------------------------------------------
extern "C" void kernel_launch(void* const* d_in, const int* in_sizes, int n_in,
                              void* d_out, int out_size)
{
    const float* x      = (const float*)d_in[0];
    const float* w_qkv  = (const float*)d_in[1];
    const float* w_proj = (const float*)d_in[2];
    float* out = (float*)d_out;

    ushort_t *xf, *wqkvf, *wprojf, *qkvf, *vtf, *ctxf;
    float *qkv, *attn_fb;
    cudaGetSymbolAddress((void**)&xf, g_xf);
    cudaGetSymbolAddress((void**)&wqkvf, g_wqkvf);
    cudaGetSymbolAddress((void**)&wprojf, g_wprojf);
    cudaGetSymbolAddress((void**)&qkv, g_qkv);
    cudaGetSymbolAddress((void**)&qkvf, g_qkvf);
    cudaGetSymbolAddress((void**)&vtf, g_vtf);
    cudaGetSymbolAddress((void**)&ctxf, g_ctxf);
    cudaGetSymbolAddress((void**)&attn_fb, g_attn_fallback);

    const size_t out_elems = (size_t)BB * TT * DM;
    float* attn = ((size_t)out_size > out_elems) ? (out + out_elems) : attn_fb;

    const int SMEM128 = 3 * (128 * 64 + 128 * 64);   // 49152
    const int SMEMAT  = 81920 + 2048;                // 83968
    cudaFuncSetAttribute(gemm_mma3<128>, cudaFuncAttributeMaxDynamicSharedMemorySize, SMEM128);
    cudaFuncSetAttribute(attn_fused, cudaFuncAttributeMaxDynamicSharedMemorySize, SMEMAT);

    const int M = BB * TT;

    // 0) fp16 conversions
    conv_arr<<<M * DM / 4 / 256, 256>>>((const float4*)x, (ushort4*)xf, M * DM / 4);
    conv_arr<<<3 * DM * DM / 4 / 256, 256>>>((const float4*)w_qkv, (ushort4*)wqkvf, 3 * DM * DM / 4);
    conv_arr<<<DM * DM / 4 / 256, 256>>>((const float4*)w_proj, (ushort4*)wprojf, DM * DM / 4);

    // 1) qkv = x @ w_qkv^T
    gemm_mma3<128><<<dim3(3 * DM / 128, M / 128, 1), 256, SMEM128>>>(
        xf, wqkvf, qkv, DM, DM, DM, 3 * DM, 1.0f);

    // 2) fp16 qkv + transpose V
    conv_arr<<<M * 3 * DM / 4 / 256, 256>>>((const float4*)qkv, (ushort4*)qkvf, M * 3 * DM / 4);
    transpose_v<<<dim3(DH / 32, TT / 32, BB * NH), dim3(32, 8)>>>(qkv, vtf);

    // 3) fused flash attention: attn fp32 + ctxf fp16
    attn_fused<<<dim3(16, 1, BB * NH), 256, SMEMAT>>>(qkvf, vtf, attn, ctxf);

    // 4) out = ctx @ w_proj^T
    gemm_mma3<128><<<dim3(DM / 128, M / 128, 1), 256, SMEM128>>>(
        ctxf, wprojf, out, DM, DM, DM, DM, 1.0f);
}

// round 8
// speedup vs baseline: 3.8478x; 1.0223x over previous
#include <cuda_runtime.h>
#include <cuda_fp16.h>
#include <cstdint>
#include <math.h>

#define NH 16
#define DM 1024
#define DH 64
#define BB 2
#define TT 2048

typedef unsigned short ushort_t;

// ---------------------------------------------------------------------------
__device__ ushort_t g_xf[(size_t)BB * TT * DM];
__device__ ushort_t g_wqkvf[(size_t)3 * DM * DM];
__device__ ushort_t g_wprojf[(size_t)DM * DM];
__device__ ushort_t g_qkvf[(size_t)BB * TT * 3 * DM];
__device__ ushort_t g_vtf[(size_t)BB * NH * DH * TT];   // V^T per head [64][2048]
__device__ ushort_t g_ctxf[(size_t)BB * TT * DM];
__device__ float    g_attn_fallback[(size_t)BB * NH * TT * TT];

// ---------------------------------------------------------------------------
__device__ __forceinline__ uint32_t smem_u32(const void* p) {
    uint32_t a;
    asm("{ .reg .u64 t; cvta.to.shared.u64 t, %1; cvt.u32.u64 %0, t; }" : "=r"(a) : "l"(p));
    return a;
}
__device__ __forceinline__ void cp16(uint32_t dst, const void* src) {
    unsigned long long g = (unsigned long long)__cvta_generic_to_global(src);
    asm volatile("cp.async.cg.shared.global [%0], [%1], 16;" :: "r"(dst), "l"(g));
}
#define CP_COMMIT() asm volatile("cp.async.commit_group;" ::: "memory")
#define CP_WAIT0()  asm volatile("cp.async.wait_group 0;" ::: "memory")
#define CP_WAIT1()  asm volatile("cp.async.wait_group 1;" ::: "memory")
#define CP_WAIT2()  asm volatile("cp.async.wait_group 2;" ::: "memory")

__device__ __forceinline__ void ldsm4(uint32_t* r, uint32_t addr) {
    asm volatile("ldmatrix.sync.aligned.m8n8.x4.shared.b16 {%0,%1,%2,%3}, [%4];"
        : "=r"(r[0]), "=r"(r[1]), "=r"(r[2]), "=r"(r[3]) : "r"(addr));
}
__device__ __forceinline__ void mma16816(float* c, const uint32_t* a, uint32_t b0, uint32_t b1) {
    asm volatile("mma.sync.aligned.m16n8k16.row.col.f32.f16.f16.f32 "
        "{%0,%1,%2,%3}, {%4,%5,%6,%7}, {%8,%9}, {%0,%1,%2,%3};"
        : "+f"(c[0]), "+f"(c[1]), "+f"(c[2]), "+f"(c[3])
        : "r"(a[0]), "r"(a[1]), "r"(a[2]), "r"(a[3]), "r"(b0), "r"(b1));
}
__device__ __forceinline__ ushort_t f2h(float x) {
    return __half_as_ushort(__float2half_rn(x));
}
__device__ __forceinline__ uint32_t f2h2(float a, float b) {
    __half2 h = __floats2half2_rn(a, b);
    return *(uint32_t*)&h;
}

// ---------------------------------------------------------------------------
__global__ __launch_bounds__(256) void conv_arr(const float4* __restrict__ in,
                                                ushort4* __restrict__ o, int n4) {
    int i = blockIdx.x * 256 + threadIdx.x;
    if (i < n4) {
        float4 v = in[i];
        o[i] = make_ushort4(f2h(v.x), f2h(v.y), f2h(v.z), f2h(v.w));
    }
}

// Transpose V from fp16 qkvf: vtf[(bh*64+d)*2048 + t] = qkvf[(b*T+t)*3072 + 2048 + h*64 + d]
__global__ __launch_bounds__(256) void transpose_v(const ushort_t* __restrict__ qkvf,
                                                   ushort_t* __restrict__ vtf) {
    __shared__ ushort_t tile[32][34];
    int bh = blockIdx.z;
    int b = bh >> 4, h = bh & 15;
    int t0 = blockIdx.y * 32, d0 = blockIdx.x * 32;
    int tx = threadIdx.x, ty = threadIdx.y;
#pragma unroll
    for (int j = 0; j < 4; j++) {
        int t = t0 + ty + j * 8;
        int d = d0 + tx;
        tile[ty + j * 8][tx] = qkvf[((size_t)b * TT + t) * (3 * DM) + 2 * DM + h * DH + d];
    }
    __syncthreads();
#pragma unroll
    for (int j = 0; j < 4; j++) {
        int d = d0 + ty + j * 8;
        int t = t0 + tx;
        vtf[((size_t)bh * DH + d) * TT + t] = tile[tx][ty + j * 8];
    }
}

// ---------------------------------------------------------------------------
// fp16 mma.sync GEMM (dense): C[M,N] = A[M,K] * B[N,K]^T. KC=32, 3-stage
// cp.async, XOR-swizzled smem. BM=128, BN=128. 8 warps.
// OUTHALF: 0 -> fp32 C, 1 -> fp16 C (packed stores).
// ---------------------------------------------------------------------------
template <int OUTHALF>
__global__ __launch_bounds__(256, 2) void gemm_mma3(
    const ushort_t* __restrict__ Ap, const ushort_t* __restrict__ Bp,
    void* __restrict__ Cv, int K, int lda, int ldb, int ldc)
{
    constexpr int BN = 128;
    constexpr int NP = BN / 32;
    constexpr int A_BYTES = 128 * 64;
    constexpr int B_BYTES = BN * 64;
    constexpr int STAGE = A_BYTES + B_BYTES;
    constexpr int OFF_B = A_BYTES;

    int bx = blockIdx.x, by = blockIdx.y;
    int row0 = by * 128, col0 = bx * BN;

    extern __shared__ char smraw[];
    uint32_t smb = smem_u32(smraw);

    int tid = threadIdx.x;
    int wid = tid >> 5, L = tid & 31;
    int warp_row = (wid & 3) * 32;
    int warp_col = (wid >> 2) * (BN / 2);

    int nc = K >> 5;
    int ldrow = ((L >> 3) & 1) * 8 + (L & 7);
    int ldk   = L >> 4;

    float acc[2][2 * NP][4];
#pragma unroll
    for (int i = 0; i < 2; i++)
#pragma unroll
        for (int j = 0; j < 2 * NP; j++)
#pragma unroll
            for (int q = 0; q < 4; q++) acc[i][j][q] = 0.f;

    auto load_stage = [&](uint32_t sb, int k0) {
#pragma unroll
        for (int j = 0; j < 2; j++) {
            int slot = tid * 2 + j;
            int r = slot >> 2, c = slot & 3;
            uint32_t d = (uint32_t)(r * 64 + ((c ^ ((r >> 1) & 3)) * 16));
            cp16(sb + d, Ap + (size_t)(row0 + r) * lda + k0 + c * 8);
        }
#pragma unroll
        for (int j = 0; j < 2; j++) {
            int slot = tid * 2 + j;
            int r = slot >> 2, c = slot & 3;
            uint32_t d = (uint32_t)(r * 64 + ((c ^ ((r >> 1) & 3)) * 16));
            cp16(sb + OFF_B + d, Bp + (size_t)(col0 + r) * ldb + k0 + c * 8);
        }
    };

#pragma unroll
    for (int s = 0; s < 2; s++) {
        if (s < nc) load_stage(smb + s * STAGE, s * 32);
        CP_COMMIT();
    }

    for (int ch = 0; ch < nc; ch++) {
        int sN = ch + 2;
        if (sN < nc) load_stage(smb + (sN % 3) * STAGE, sN * 32);
        CP_COMMIT();
        CP_WAIT2();
        __syncthreads();

        uint32_t sb = smb + (ch % 3) * STAGE;
#pragma unroll
        for (int s = 0; s < 2; s++) {
            int cbase = 2 * s + ldk;
            uint32_t af[2][4];
#pragma unroll
            for (int mt = 0; mt < 2; mt++) {
                int rr = warp_row + mt * 16 + ldrow;
                uint32_t ra = (uint32_t)(rr * 64 + ((cbase ^ ((rr >> 1) & 3)) * 16));
                ldsm4(af[mt], sb + ra);
            }
#pragma unroll
            for (int np = 0; np < NP; np++) {
                int rr = warp_col + np * 16 + ldrow;
                uint32_t rb = (uint32_t)(rr * 64 + ((cbase ^ ((rr >> 1) & 3)) * 16));
                uint32_t bf[4];
                ldsm4(bf, sb + OFF_B + rb);
#pragma unroll
                for (int mt = 0; mt < 2; mt++) {
                    mma16816(acc[mt][2 * np],     af[mt], bf[0], bf[2]);
                    mma16816(acc[mt][2 * np + 1], af[mt], bf[1], bf[3]);
                }
            }
        }
        __syncthreads();
    }

#pragma unroll
    for (int mt = 0; mt < 2; mt++) {
        int r0g = row0 + warp_row + mt * 16 + (L >> 2);
#pragma unroll
        for (int nt = 0; nt < 2 * NP; nt++) {
            int cg = col0 + warp_col + nt * 8 + (L & 3) * 2;
            if (OUTHALF) {
                ushort_t* C = (ushort_t*)Cv;
                *(uint32_t*)(C + (size_t)r0g * ldc + cg)       = f2h2(acc[mt][nt][0], acc[mt][nt][1]);
                *(uint32_t*)(C + (size_t)(r0g + 8) * ldc + cg) = f2h2(acc[mt][nt][2], acc[mt][nt][3]);
            } else {
                float* C = (float*)Cv;
                *(float2*)(C + (size_t)r0g * ldc + cg) =
                    make_float2(acc[mt][nt][0], acc[mt][nt][1]);
                *(float2*)(C + (size_t)(r0g + 8) * ldc + cg) =
                    make_float2(acc[mt][nt][2], acc[mt][nt][3]);
            }
        }
    }
}

// ---------------------------------------------------------------------------
// Fused two-pass flash attention per (bh, 128-row Q tile).
// ---------------------------------------------------------------------------
__global__ __launch_bounds__(256) void attn_fused(
    const ushort_t* __restrict__ qkvf, const ushort_t* __restrict__ vtf,
    float* __restrict__ attn, ushort_t* __restrict__ ctxf)
{
    constexpr int QOF = 0;
    constexpr int KST = 16384;
    constexpr int KSTG = 16384;
    constexpr int VST = 49152;
    constexpr int VSTG = 16384;
    constexpr int RED = 81920;
    const int ldq = 3 * DM;

    int by = 15 - blockIdx.x;
    int bh = blockIdx.z;
    int b = bh >> 4, h = bh & 15;
    int row0 = by * 128;

    const ushort_t* Q  = qkvf + (size_t)b * TT * 3 * DM + h * DH;
    const ushort_t* Kp = Q + DM;
    const ushort_t* Vt = vtf + (size_t)bh * DH * TT;
    float* Cb = attn + (size_t)bh * TT * TT;

    extern __shared__ char smraw[];
    uint32_t smb = smem_u32(smraw);
    float* mbuf = (float*)(smraw + RED);
    float* sbuf = (float*)(smraw + RED + 1024);

    int tid = threadIdx.x;
    int wid = tid >> 5, L = tid & 31;
    int warp_row = (wid & 3) * 32;
    int wc = wid >> 2;
    int warp_col = wc * 64;
    int ldrow = ((L >> 3) & 1) * 8 + (L & 7);
    int ldk   = L >> 4;

    int lrow = tid >> 1;
    int lc0  = (tid & 1) * 4;
    int vrow = tid >> 2;
    int vc0  = (tid & 3) * 4;

    // ======================= PASS A: stats =======================
#pragma unroll
    for (int j = 0; j < 4; j++) {
        int c = lc0 + j;
        uint32_t d = (uint32_t)(lrow * 128 + ((c ^ (lrow & 7)) * 16));
        cp16(smb + QOF + d, Q + (size_t)(row0 + lrow) * ldq + c * 8);
        cp16(smb + KST + d, Kp + (size_t)lrow * ldq + c * 8);
    }
    CP_COMMIT();

    float mA[2][2], sA[2][2];
#pragma unroll
    for (int i = 0; i < 2; i++)
#pragma unroll
        for (int j = 0; j < 2; j++) { mA[i][j] = -1e30f; sA[i][j] = 0.f; }

    for (int jt = 0; jt <= by; jt++) {
        if (jt < by) {
            uint32_t sb = smb + KST + ((jt + 1) & 1) * KSTG;
#pragma unroll
            for (int j = 0; j < 4; j++) {
                int c = lc0 + j;
                uint32_t d = (uint32_t)(lrow * 128 + ((c ^ (lrow & 7)) * 16));
                cp16(sb + d, Kp + (size_t)((jt + 1) * 128 + lrow) * ldq + c * 8);
            }
        }
        CP_COMMIT();
        CP_WAIT1();
        __syncthreads();

        float acc[2][8][4];
#pragma unroll
        for (int i = 0; i < 2; i++)
#pragma unroll
            for (int j = 0; j < 8; j++)
#pragma unroll
                for (int q = 0; q < 4; q++) acc[i][j][q] = 0.f;

        uint32_t kb = smb + KST + (jt & 1) * KSTG;
#pragma unroll
        for (int s = 0; s < 4; s++) {
            int cbase = 2 * s + ldk;
            uint32_t af[2][4];
#pragma unroll
            for (int mt = 0; mt < 2; mt++) {
                int rr = warp_row + mt * 16 + ldrow;
                uint32_t ra = (uint32_t)(rr * 128 + ((cbase ^ (rr & 7)) * 16));
                ldsm4(af[mt], smb + QOF + ra);
            }
#pragma unroll
            for (int np = 0; np < 4; np++) {
                int rr = warp_col + np * 16 + ldrow;
                uint32_t rb = (uint32_t)(rr * 128 + ((cbase ^ (rr & 7)) * 16));
                uint32_t bf[4];
                ldsm4(bf, kb + rb);
#pragma unroll
                for (int mt = 0; mt < 2; mt++) {
                    mma16816(acc[mt][2 * np],     af[mt], bf[0], bf[2]);
                    mma16816(acc[mt][2 * np + 1], af[mt], bf[1], bf[3]);
                }
            }
        }

        int col0 = jt * 128;
        bool diag = (jt == by);
#pragma unroll
        for (int mt = 0; mt < 2; mt++) {
#pragma unroll
            for (int inst = 0; inst < 2; inst++) {
                int rg = row0 + warp_row + mt * 16 + inst * 8 + (L >> 2);
                float vv[16];
                float tm = -1e30f;
#pragma unroll
                for (int nt = 0; nt < 8; nt++) {
#pragma unroll
                    for (int e = 0; e < 2; e++) {
                        float v = acc[mt][nt][inst * 2 + e] * 0.125f;
                        if (diag) {
                            int kg = col0 + warp_col + nt * 8 + (L & 3) * 2 + e;
                            if (kg > rg) v = -1e30f;
                        }
                        vv[nt * 2 + e] = v;
                        tm = fmaxf(tm, v);
                    }
                }
                if (tm > -1e29f) {
                    float mo = mA[mt][inst];
                    float mn = fmaxf(mo, tm);
                    float ssum = 0.f;
#pragma unroll
                    for (int i = 0; i < 16; i++) ssum += __expf(vv[i] - mn);
                    sA[mt][inst] = sA[mt][inst] * __expf(mo - mn) + ssum;
                    mA[mt][inst] = mn;
                }
            }
        }
        __syncthreads();
    }

    // quad + cross-warp stat reduction
#pragma unroll
    for (int mt = 0; mt < 2; mt++) {
#pragma unroll
        for (int inst = 0; inst < 2; inst++) {
            float m = mA[mt][inst], s = sA[mt][inst];
#pragma unroll
            for (int off = 1; off <= 2; off <<= 1) {
                float mo = __shfl_xor_sync(0xffffffffu, m, off);
                float so = __shfl_xor_sync(0xffffffffu, s, off);
                float mn = fmaxf(m, mo);
                s = s * __expf(m - mn) + so * __expf(mo - mn);
                m = mn;
            }
            if ((L & 3) == 0) {
                int row = warp_row + mt * 16 + inst * 8 + (L >> 2);
                mbuf[wc * 128 + row] = m;
                sbuf[wc * 128 + row] = s;
            }
        }
    }
    __syncthreads();

    float mF[2][2], iS[2][2];
#pragma unroll
    for (int mt = 0; mt < 2; mt++) {
#pragma unroll
        for (int inst = 0; inst < 2; inst++) {
            int row = warp_row + mt * 16 + inst * 8 + (L >> 2);
            float m0 = mbuf[row], s0 = sbuf[row];
            float m1 = mbuf[128 + row], s1 = sbuf[128 + row];
            float mn = fmaxf(m0, m1);
            float s = s0 * __expf(m0 - mn) + s1 * __expf(m1 - mn);
            mF[mt][inst] = mn;
            iS[mt][inst] = 1.0f / s;
        }
    }
    CP_WAIT0();
    __syncthreads();

    // ======================= PASS B: P write + O accum =======================
#pragma unroll
    for (int j = 0; j < 4; j++) {
        int c = lc0 + j;
        uint32_t d = (uint32_t)(lrow * 128 + ((c ^ (lrow & 7)) * 16));
        cp16(smb + KST + d, Kp + (size_t)lrow * ldq + c * 8);
    }
#pragma unroll
    for (int j = 0; j < 4; j++) {
        int c2 = vc0 + j;
        uint32_t dv = (uint32_t)(vrow * 256 + ((c2 ^ (vrow & 7)) * 16));
        cp16(smb + VST + dv, Vt + (size_t)vrow * TT + c2 * 8);
    }
    CP_COMMIT();

    float O[2][8][4];
#pragma unroll
    for (int i = 0; i < 2; i++)
#pragma unroll
        for (int j = 0; j < 8; j++)
#pragma unroll
            for (int q = 0; q < 4; q++) O[i][j][q] = 0.f;

    for (int jt = 0; jt <= by; jt++) {
        if (jt < by) {
            uint32_t sb = smb + KST + ((jt + 1) & 1) * KSTG;
            uint32_t sv = smb + VST + ((jt + 1) & 1) * VSTG;
#pragma unroll
            for (int j = 0; j < 4; j++) {
                int c = lc0 + j;
                uint32_t d = (uint32_t)(lrow * 128 + ((c ^ (lrow & 7)) * 16));
                cp16(sb + d, Kp + (size_t)((jt + 1) * 128 + lrow) * ldq + c * 8);
            }
#pragma unroll
            for (int j = 0; j < 4; j++) {
                int c2 = vc0 + j;
                uint32_t dv = (uint32_t)(vrow * 256 + ((c2 ^ (vrow & 7)) * 16));
                cp16(sv + dv, Vt + (size_t)vrow * TT + (jt + 1) * 128 + c2 * 8);
            }
        }
        CP_COMMIT();
        CP_WAIT1();
        __syncthreads();

        float acc[2][8][4];
#pragma unroll
        for (int i = 0; i < 2; i++)
#pragma unroll
            for (int j = 0; j < 8; j++)
#pragma unroll
                for (int q = 0; q < 4; q++) acc[i][j][q] = 0.f;

        uint32_t kb = smb + KST + (jt & 1) * KSTG;
#pragma unroll
        for (int s = 0; s < 4; s++) {
            int cbase = 2 * s + ldk;
            uint32_t af[2][4];
#pragma unroll
            for (int mt = 0; mt < 2; mt++) {
                int rr = warp_row + mt * 16 + ldrow;
                uint32_t ra = (uint32_t)(rr * 128 + ((cbase ^ (rr & 7)) * 16));
                ldsm4(af[mt], smb + QOF + ra);
            }
#pragma unroll
            for (int np = 0; np < 4; np++) {
                int rr = warp_col + np * 16 + ldrow;
                uint32_t rb = (uint32_t)(rr * 128 + ((cbase ^ (rr & 7)) * 16));
                uint32_t bf[4];
                ldsm4(bf, kb + rb);
#pragma unroll
                for (int mt = 0; mt < 2; mt++) {
                    mma16816(acc[mt][2 * np],     af[mt], bf[0], bf[2]);
                    mma16816(acc[mt][2 * np + 1], af[mt], bf[1], bf[3]);
                }
            }
        }

        int col0 = jt * 128;
        bool diag = (jt == by);
#pragma unroll
        for (int mt = 0; mt < 2; mt++) {
#pragma unroll
            for (int nt = 0; nt < 8; nt++) {
#pragma unroll
                for (int q = 0; q < 4; q++) {
                    int inst = q >> 1;
                    float v = acc[mt][nt][q] * 0.125f;
                    float p = __expf(v - mF[mt][inst]) * iS[mt][inst];
                    if (diag) {
                        int rg = row0 + warp_row + mt * 16 + inst * 8 + (L >> 2);
                        int kg = col0 + warp_col + nt * 8 + (L & 3) * 2 + (q & 1);
                        if (kg > rg) p = 0.f;
                    }
                    acc[mt][nt][q] = p;
                }
            }
        }

#pragma unroll
        for (int mt = 0; mt < 2; mt++) {
            int r0g = row0 + warp_row + mt * 16 + (L >> 2);
#pragma unroll
            for (int nt = 0; nt < 8; nt++) {
                int cg = col0 + warp_col + nt * 8 + (L & 3) * 2;
                *(float2*)(Cb + (size_t)r0g * TT + cg) =
                    make_float2(acc[mt][nt][0], acc[mt][nt][1]);
                *(float2*)(Cb + (size_t)(r0g + 8) * TT + cg) =
                    make_float2(acc[mt][nt][2], acc[mt][nt][3]);
            }
        }

        uint32_t kbv = smb + VST + (jt & 1) * VSTG;
#pragma unroll
        for (int g = 0; g < 4; g++) {
            uint32_t aa[2][4];
#pragma unroll
            for (int mt = 0; mt < 2; mt++) {
                aa[mt][0] = f2h2(acc[mt][2 * g][0],     acc[mt][2 * g][1]);
                aa[mt][1] = f2h2(acc[mt][2 * g][2],     acc[mt][2 * g][3]);
                aa[mt][2] = f2h2(acc[mt][2 * g + 1][0], acc[mt][2 * g + 1][1]);
                aa[mt][3] = f2h2(acc[mt][2 * g + 1][2], acc[mt][2 * g + 1][3]);
            }
            int cb = (warp_col >> 3) + 2 * g + ldk;
#pragma unroll
            for (int np2 = 0; np2 < 4; np2++) {
                int rr2 = np2 * 16 + ldrow;
                uint32_t rb = (uint32_t)(rr2 * 256 + ((cb ^ (rr2 & 7)) * 16));
                uint32_t bf[4];
                ldsm4(bf, kbv + rb);
#pragma unroll
                for (int mt = 0; mt < 2; mt++) {
                    mma16816(O[mt][2 * np2],     aa[mt], bf[0], bf[2]);
                    mma16816(O[mt][2 * np2 + 1], aa[mt], bf[1], bf[3]);
                }
            }
        }
        __syncthreads();
    }

    // zero-fill causal tail of attn
    int zt = 15 - by;
    if (zt > 0) {
        int r = tid >> 1;
        int halfc = zt * 64;
        float* base = Cb + (size_t)(row0 + r) * TT + (by + 1) * 128 + (tid & 1) * halfc;
        for (int i = 0; i < halfc; i += 4)
            *(float4*)(base + i) = make_float4(0.f, 0.f, 0.f, 0.f);
    }

    // O cross-warp reduce + ctxf write
    float* Ob = (float*)(smraw + KST);
    if (wc == 1) {
#pragma unroll
        for (int mt = 0; mt < 2; mt++) {
            int row = warp_row + mt * 16 + (L >> 2);
#pragma unroll
            for (int nt = 0; nt < 8; nt++) {
                int col = nt * 8 + (L & 3) * 2;
                Ob[row * 64 + col]           = O[mt][nt][0];
                Ob[row * 64 + col + 1]       = O[mt][nt][1];
                Ob[(row + 8) * 64 + col]     = O[mt][nt][2];
                Ob[(row + 8) * 64 + col + 1] = O[mt][nt][3];
            }
        }
    }
    __syncthreads();
    if (wc == 0) {
#pragma unroll
        for (int mt = 0; mt < 2; mt++) {
            int row = warp_row + mt * 16 + (L >> 2);
#pragma unroll
            for (int nt = 0; nt < 8; nt++) {
                int col = nt * 8 + (L & 3) * 2;
                float v0 = O[mt][nt][0] + Ob[row * 64 + col];
                float v1 = O[mt][nt][1] + Ob[row * 64 + col + 1];
                float v2 = O[mt][nt][2] + Ob[(row + 8) * 64 + col];
                float v3 = O[mt][nt][3] + Ob[(row + 8) * 64 + col + 1];
                size_t a0 = ((size_t)b * TT + row0 + row) * DM + h * DH + col;
                size_t a1 = ((size_t)b * TT + row0 + row + 8) * DM + h * DH + col;
                *(uint32_t*)(ctxf + a0) = f2h2(v0, v1);
                *(uint32_t*)(ctxf + a1) = f2h2(v2, v3);
            }
        }
    }
}

// ---------------------------------------------------------------------------
extern "C" void kernel_launch(void* const* d_in, const int* in_sizes, int n_in,
                              void* d_out, int out_size)
{
    const float* x      = (const float*)d_in[0];
    const float* w_qkv  = (const float*)d_in[1];
    const float* w_proj = (const float*)d_in[2];
    float* out = (float*)d_out;

    ushort_t *xf, *wqkvf, *wprojf, *qkvf, *vtf, *ctxf;
    float *attn_fb;
    cudaGetSymbolAddress((void**)&xf, g_xf);
    cudaGetSymbolAddress((void**)&wqkvf, g_wqkvf);
    cudaGetSymbolAddress((void**)&wprojf, g_wprojf);
    cudaGetSymbolAddress((void**)&qkvf, g_qkvf);
    cudaGetSymbolAddress((void**)&vtf, g_vtf);
    cudaGetSymbolAddress((void**)&ctxf, g_ctxf);
    cudaGetSymbolAddress((void**)&attn_fb, g_attn_fallback);

    const size_t out_elems = (size_t)BB * TT * DM;
    float* attn = ((size_t)out_size > out_elems) ? (out + out_elems) : attn_fb;

    const int SMEM128 = 3 * (128 * 64 + 128 * 64);   // 49152
    const int SMEMAT  = 81920 + 2048;                // 83968
    cudaFuncSetAttribute(gemm_mma3<0>, cudaFuncAttributeMaxDynamicSharedMemorySize, SMEM128);
    cudaFuncSetAttribute(gemm_mma3<1>, cudaFuncAttributeMaxDynamicSharedMemorySize, SMEM128);
    cudaFuncSetAttribute(attn_fused, cudaFuncAttributeMaxDynamicSharedMemorySize, SMEMAT);

    const int M = BB * TT;

    // 0) fp16 conversions (inputs only)
    conv_arr<<<M * DM / 4 / 256, 256>>>((const float4*)x, (ushort4*)xf, M * DM / 4);
    conv_arr<<<3 * DM * DM / 4 / 256, 256>>>((const float4*)w_qkv, (ushort4*)wqkvf, 3 * DM * DM / 4);
    conv_arr<<<DM * DM / 4 / 256, 256>>>((const float4*)w_proj, (ushort4*)wprojf, DM * DM / 4);

    // 1) qkvf = fp16(x @ w_qkv^T)  -- direct fp16 epilogue
    gemm_mma3<1><<<dim3(3 * DM / 128, M / 128, 1), 256, SMEM128>>>(
        xf, wqkvf, qkvf, DM, DM, DM, 3 * DM);

    // 2) transpose V (fp16 -> fp16)
    transpose_v<<<dim3(DH / 32, TT / 32, BB * NH), dim3(32, 8)>>>(qkvf, vtf);

    // 3) fused flash attention: attn fp32 + ctxf fp16
    attn_fused<<<dim3(16, 1, BB * NH), 256, SMEMAT>>>(qkvf, vtf, attn, ctxf);

    // 4) out = ctx @ w_proj^T (fp32 out)
    gemm_mma3<0><<<dim3(DM / 128, M / 128, 1), 256, SMEM128>>>(
        ctxf, wprojf, out, DM, DM, DM, DM);
}